// round 5
// baseline (speedup 1.0000x reference)
#include <cuda_runtime.h>
#include <cuda_bf16.h>
#include <math.h>
#include <stdint.h>

// Problem constants
#define BB   2
#define TT   2048
#define CC   1024
#define HH   16
#define HD   64
#define HD2  32
#define MROWS (BB*TT)          // 4096
#define QKVW (3*CC)            // 3072

// Scratch (allocation-free rule: __device__ globals)
__device__ float g_qkv[(size_t)MROWS * QKVW];               // [B*T, 3C] fp32
// bf16 hi/lo of x and attention output, [M][K] row-major
__device__ __nv_bfloat16 g_xh[(size_t)MROWS * CC],  g_xl[(size_t)MROWS * CC];
__device__ __nv_bfloat16 g_ath[(size_t)MROWS * CC], g_atl[(size_t)MROWS * CC];
// transposed weights, bf16 hi/lo, [N][K]
__device__ __nv_bfloat16 g_wqh[(size_t)QKVW * CC], g_wql[(size_t)QKVW * CC];
__device__ __nv_bfloat16 g_wph[(size_t)CC * CC],   g_wpl[(size_t)CC * CC];
// Head-contiguous bf16 hi/lo splits of roped q, k and v: [b*H+h][T][64]
#define HELEMS ((size_t)BB * HH * TT * HD)
__device__ __nv_bfloat16 g_qh[HELEMS], g_ql[HELEMS];
__device__ __nv_bfloat16 g_kh[HELEMS], g_kl[HELEMS];
__device__ __nv_bfloat16 g_vh[HELEMS], g_vl[HELEMS];

// ---------------------------------------------------------------------------
// Helpers
// ---------------------------------------------------------------------------
__device__ __forceinline__ void split2(float x, float y, unsigned &h, unsigned &l)
{
    __nv_bfloat16 hx = __float2bfloat16(x), hy = __float2bfloat16(y);
    float rx = x - __bfloat162float(hx);
    float ry = y - __bfloat162float(hy);
    __nv_bfloat16 lx = __float2bfloat16(rx), ly = __float2bfloat16(ry);
    h = (unsigned)*(unsigned short*)&hx | ((unsigned)*(unsigned short*)&hy << 16);
    l = (unsigned)*(unsigned short*)&lx | ((unsigned)*(unsigned short*)&ly << 16);
}

__device__ __forceinline__ void split1(float x, __nv_bfloat16 &h, __nv_bfloat16 &l)
{
    h = __float2bfloat16(x);
    l = __float2bfloat16(x - __bfloat162float(h));
}

__device__ __forceinline__ void ldsm_x4(unsigned r[4], unsigned addr)
{
    asm volatile("ldmatrix.sync.aligned.m8n8.x4.shared.b16 {%0,%1,%2,%3}, [%4];"
                 : "=r"(r[0]), "=r"(r[1]), "=r"(r[2]), "=r"(r[3]) : "r"(addr));
}

__device__ __forceinline__ void ldsm_x4_t(unsigned r[4], unsigned addr)
{
    asm volatile("ldmatrix.sync.aligned.m8n8.x4.trans.shared.b16 {%0,%1,%2,%3}, [%4];"
                 : "=r"(r[0]), "=r"(r[1]), "=r"(r[2]), "=r"(r[3]) : "r"(addr));
}

__device__ __forceinline__ void mma_bf16(float d[4], const unsigned a[4], unsigned b0, unsigned b1)
{
    asm volatile("mma.sync.aligned.m16n8k16.row.col.f32.bf16.bf16.f32 "
                 "{%0,%1,%2,%3}, {%4,%5,%6,%7}, {%8,%9}, {%0,%1,%2,%3};"
                 : "+f"(d[0]), "+f"(d[1]), "+f"(d[2]), "+f"(d[3])
                 : "r"(a[0]), "r"(a[1]), "r"(a[2]), "r"(a[3]), "r"(b0), "r"(b1));
}

__device__ __forceinline__ void cp16(unsigned dst, const void* src)
{
    asm volatile("cp.async.cg.shared.global [%0], [%1], 16;" :: "r"(dst), "l"(src));
}
#define CP_COMMIT  asm volatile("cp.async.commit_group;" ::: "memory")
#define CP_WAIT(n) asm volatile("cp.async.wait_group %0;" :: "n"(n) : "memory")

// ---------------------------------------------------------------------------
// Prep kernels
// ---------------------------------------------------------------------------
__global__ __launch_bounds__(256) void convsplit(
    const float* __restrict__ X, __nv_bfloat16* __restrict__ Xh,
    __nv_bfloat16* __restrict__ Xl)
{
    int i = (blockIdx.x * 256 + threadIdx.x) * 4;
    float4 v = *(const float4*)(X + i);
    unsigned h0, l0, h1, l1;
    split2(v.x, v.y, h0, l0);
    split2(v.z, v.w, h1, l1);
    *(uint2*)(Xh + i) = make_uint2(h0, h1);
    *(uint2*)(Xl + i) = make_uint2(l0, l1);
}

// W [K][N] fp32 -> Wh/Wl [N][K] bf16  (32x32 smem tile transpose)
__global__ __launch_bounds__(256) void transpose_split(
    const float* __restrict__ W, __nv_bfloat16* __restrict__ Wh,
    __nv_bfloat16* __restrict__ Wl, int K, int N)
{
    __shared__ float tile[32][33];
    const int n0 = blockIdx.x * 32, k0 = blockIdx.y * 32;
    const int tx = threadIdx.x & 31, ty = threadIdx.x >> 5;   // 32 x 8
    #pragma unroll
    for (int i = 0; i < 32; i += 8)
        tile[ty + i][tx] = W[(size_t)(k0 + ty + i) * N + n0 + tx];
    __syncthreads();
    #pragma unroll
    for (int i = 0; i < 32; i += 8) {
        float v = tile[tx][ty + i];       // = W[k0+tx][n0+ty+i]
        __nv_bfloat16 h, l;
        split1(v, h, l);
        Wh[(size_t)(n0 + ty + i) * K + k0 + tx] = h;
        Wl[(size_t)(n0 + ty + i) * K + k0 + tx] = l;
    }
}

// ---------------------------------------------------------------------------
// Split-bf16 mma.sync GEMM on pre-split operands:
//   C[M,N] = A@W^T + bias;  A hi/lo [M][K] k-major; W hi/lo [N][K] k-major.
// CTA tile 128x128, BK=32, 256 threads (8 warps as 2x4, warp tile 64x32).
// cp.async double-buffered smem; 80B padded rows (16B aligned, ldmatrix
// conflict-free). 3-term split accumulate: AhBh + AhBl + AlBh.
// ---------------------------------------------------------------------------
#define GROW   80                     // bytes per smem row (32 bf16 + pad)
#define GMAT   (128*GROW)             // 10240 B per matrix
#define GSTAGE (4*GMAT)               // Ah,Al,Bh,Bl
#define GSMEM  (2*GSTAGE)             // 81920 B

__device__ __forceinline__ void g2_fill(
    unsigned sb,
    const __nv_bfloat16* __restrict__ Ah_g, const __nv_bfloat16* __restrict__ Al_g,
    const __nv_bfloat16* __restrict__ Bh_g, const __nv_bfloat16* __restrict__ Bl_g,
    int row0, int col0, int K, int kbase, int tid)
{
    #pragma unroll
    for (int it = 0; it < 2; ++it) {
        int idx = it * 256 + tid;          // 0..511
        int r = idx >> 2;                  // 0..127
        int c = idx & 3;                   // 16B chunk
        unsigned doff = (unsigned)(r * GROW + c * 16);
        const size_t ak = (size_t)(row0 + r) * K + kbase + c * 8;
        const size_t bk = (size_t)(col0 + r) * K + kbase + c * 8;
        cp16(sb + doff,            Ah_g + ak);
        cp16(sb + GMAT + doff,     Al_g + ak);
        cp16(sb + 2 * GMAT + doff, Bh_g + bk);
        cp16(sb + 3 * GMAT + doff, Bl_g + bk);
    }
}

__global__ __launch_bounds__(256) void bgemm2(
    const __nv_bfloat16* __restrict__ Ah_g, const __nv_bfloat16* __restrict__ Al_g,
    const __nv_bfloat16* __restrict__ Bh_g, const __nv_bfloat16* __restrict__ Bl_g,
    const float* __restrict__ bias, float* __restrict__ Cm,
    int M, int N, int K)
{
    extern __shared__ __align__(16) char smem[];
    const unsigned sb0 = (unsigned)__cvta_generic_to_shared(smem);

    const int tid  = threadIdx.x;
    const int lane = tid & 31;
    const int wid  = tid >> 5;
    const int wm   = wid >> 2;          // 0..1
    const int wn   = wid & 3;           // 0..3
    const int row0 = blockIdx.y * 128;
    const int col0 = blockIdx.x * 128;

    float acc[4][4][4];
    #pragma unroll
    for (int mi = 0; mi < 4; mi++)
        #pragma unroll
        for (int ni = 0; ni < 4; ni++)
            #pragma unroll
            for (int e = 0; e < 4; e++) acc[mi][ni][e] = 0.f;

    const int KT = K >> 5;              // 32-wide chunks

    g2_fill(sb0, Ah_g, Al_g, Bh_g, Bl_g, row0, col0, K, 0, tid);
    CP_COMMIT;

    const unsigned aoff = (unsigned)((wm * 64 + (lane & 15)) * GROW + (lane >> 4) * 16);
    const unsigned boff = (unsigned)(2 * GMAT + (wn * 32 + (lane & 15)) * GROW + (lane >> 4) * 16);

    for (int kt = 0; kt < KT; ++kt) {
        const unsigned sb = sb0 + (unsigned)(kt & 1) * GSTAGE;

        if (kt + 1 < KT) {
            g2_fill(sb0 + (unsigned)((kt + 1) & 1) * GSTAGE,
                    Ah_g, Al_g, Bh_g, Bl_g, row0, col0, K, (kt + 1) * 32, tid);
            CP_COMMIT;
            CP_WAIT(1);
        } else {
            CP_WAIT(0);
        }
        __syncthreads();

        #pragma unroll
        for (int kc = 0; kc < 2; ++kc) {
            unsigned ah[4][4], al[4][4], bh[2][4], bl[2][4];
            #pragma unroll
            for (int n2 = 0; n2 < 2; ++n2) {
                ldsm_x4(bh[n2], sb + boff + n2 * 16 * GROW + kc * 32);
                ldsm_x4(bl[n2], sb + boff + GMAT + n2 * 16 * GROW + kc * 32);
            }
            #pragma unroll
            for (int mi = 0; mi < 4; ++mi) {
                ldsm_x4(ah[mi], sb + aoff + mi * 16 * GROW + kc * 32);
                ldsm_x4(al[mi], sb + aoff + GMAT + mi * 16 * GROW + kc * 32);
            }
            #pragma unroll
            for (int mi = 0; mi < 4; ++mi)
                #pragma unroll
                for (int n2 = 0; n2 < 2; ++n2) {
                    mma_bf16(acc[mi][2 * n2],     ah[mi], bh[n2][0], bh[n2][2]);
                    mma_bf16(acc[mi][2 * n2],     ah[mi], bl[n2][0], bl[n2][2]);
                    mma_bf16(acc[mi][2 * n2],     al[mi], bh[n2][0], bh[n2][2]);
                    mma_bf16(acc[mi][2 * n2 + 1], ah[mi], bh[n2][1], bh[n2][3]);
                    mma_bf16(acc[mi][2 * n2 + 1], ah[mi], bl[n2][1], bl[n2][3]);
                    mma_bf16(acc[mi][2 * n2 + 1], al[mi], bh[n2][1], bh[n2][3]);
                }
        }
        __syncthreads();
    }

    const int g  = lane >> 2;
    const int tq = lane & 3;
    #pragma unroll
    for (int mi = 0; mi < 4; mi++) {
        const int r0 = row0 + wm * 64 + mi * 16 + g;
        #pragma unroll
        for (int ni = 0; ni < 4; ni++) {
            const int c = col0 + wn * 32 + (ni >> 1) * 16 + (ni & 1) * 8 + tq * 2;
            const float bz0 = bias[c], bz1 = bias[c + 1];
            *(float2*)(Cm + (size_t)r0 * N + c) =
                make_float2(acc[mi][ni][0] + bz0, acc[mi][ni][1] + bz1);
            *(float2*)(Cm + (size_t)(r0 + 8) * N + c) =
                make_float2(acc[mi][ni][2] + bz0, acc[mi][ni][3] + bz1);
        }
    }
}

// ---------------------------------------------------------------------------
// RoPE + split to bf16 hi/lo, head-contiguous layout [b*H+h][T][64].
// ---------------------------------------------------------------------------
__global__ __launch_bounds__(512) void rope_split(
    const float* __restrict__ qkv,
    const float* __restrict__ cosf, const float* __restrict__ sinf,
    __nv_bfloat16* __restrict__ qh, __nv_bfloat16* __restrict__ ql,
    __nv_bfloat16* __restrict__ kh, __nv_bfloat16* __restrict__ kl,
    __nv_bfloat16* __restrict__ vh, __nv_bfloat16* __restrict__ vl)
{
    const int bt  = blockIdx.x;
    const int b   = bt / TT;
    const int t   = bt % TT;
    const int tid = threadIdx.x;
    const int h   = tid >> 5;
    const int d   = tid & 31;

    const float c = cosf[t * HD2 + d];
    const float s = sinf[t * HD2 + d];

    const float* base = qkv + (size_t)bt * QKVW;
    const size_t dst = ((size_t)(b * HH + h) * TT + t) * HD + d;

    float q1 = base[h * HD + d], q2 = base[h * HD + d + HD2];
    float qr1 = (q1 * c - q2 * s) * 0.125f;
    float qr2 = (q1 * s + q2 * c) * 0.125f;
    split1(qr1, qh[dst], ql[dst]);
    split1(qr2, qh[dst + HD2], ql[dst + HD2]);

    float k1 = base[CC + h * HD + d], k2 = base[CC + h * HD + d + HD2];
    float kr1 = k1 * c - k2 * s;
    float kr2 = k1 * s + k2 * c;
    split1(kr1, kh[dst], kl[dst]);
    split1(kr2, kh[dst + HD2], kl[dst + HD2]);

    float v1 = base[2 * CC + h * HD + d], v2 = base[2 * CC + h * HD + d + HD2];
    split1(v1, vh[dst], vl[dst]);
    split1(v2, vh[dst + HD2], vl[dst + HD2]);
}

// ---------------------------------------------------------------------------
// Tensor-core flash attention (split-bf16, causal). Outputs bf16 hi/lo.
// Br=64 (4 warps x 16 rows), Bc=64. grid=(T/64, B*H), 128 threads.
// ---------------------------------------------------------------------------
#define KSTR  72
#define KSTR2 144

__global__ __launch_bounds__(128) void attn_mma(
    const __nv_bfloat16* __restrict__ qh_g, const __nv_bfloat16* __restrict__ ql_g,
    const __nv_bfloat16* __restrict__ kh_g, const __nv_bfloat16* __restrict__ kl_g,
    const __nv_bfloat16* __restrict__ vh_g, const __nv_bfloat16* __restrict__ vl_g,
    __nv_bfloat16* __restrict__ oh_g, __nv_bfloat16* __restrict__ ol_g)
{
    __shared__ __align__(16) __nv_bfloat16 sKh[64 * KSTR];
    __shared__ __align__(16) __nv_bfloat16 sKl[64 * KSTR];
    __shared__ __align__(16) __nv_bfloat16 sVh[64 * KSTR];
    __shared__ __align__(16) __nv_bfloat16 sVl[64 * KSTR];

    const int iTile = gridDim.x - 1 - blockIdx.x;   // heavy tiles first
    const int bh    = blockIdx.y;
    const int b = bh / HH, h = bh % HH;
    const int tid  = threadIdx.x;
    const int lane = tid & 31;
    const int wid  = tid >> 5;
    const int wr   = wid * 16;
    const int i0   = iTile * 64;
    const int g    = lane >> 2;
    const int tq   = lane & 3;

    const size_t hoff = (size_t)bh * TT * HD;

    const unsigned bKh = (unsigned)__cvta_generic_to_shared(sKh);
    const unsigned bKl = (unsigned)__cvta_generic_to_shared(sKl);
    const unsigned bVh = (unsigned)__cvta_generic_to_shared(sVh);
    const unsigned bVl = (unsigned)__cvta_generic_to_shared(sVl);

    {
        const uint4* qhp = (const uint4*)(qh_g + hoff + (size_t)i0 * HD);
        const uint4* qlp = (const uint4*)(ql_g + hoff + (size_t)i0 * HD);
        #pragma unroll
        for (int it = 0; it < 4; ++it) {
            int idx = it * 128 + tid;
            int r = idx >> 3, c8 = (idx & 7) * 8;
            *(uint4*)&sKh[r * KSTR + c8] = qhp[idx];
            *(uint4*)&sKl[r * KSTR + c8] = qlp[idx];
        }
    }
    __syncthreads();

    unsigned qhf[4][4], qlf[4][4];
    {
        const unsigned aoffq = (unsigned)((wr + (lane & 15)) * KSTR2 + (lane >> 4) * 16);
        #pragma unroll
        for (int kc = 0; kc < 4; ++kc) {
            ldsm_x4(qhf[kc], bKh + aoffq + kc * 32);
            ldsm_x4(qlf[kc], bKl + aoffq + kc * 32);
        }
    }

    float m0 = -INFINITY, m1 = -INFINITY, l0 = 0.f, l1 = 0.f;
    float o[8][4];
    #pragma unroll
    for (int ni = 0; ni < 8; ni++)
        #pragma unroll
        for (int e = 0; e < 4; e++) o[ni][e] = 0.f;

    const uint4* khp = (const uint4*)(kh_g + hoff);
    const uint4* klp = (const uint4*)(kl_g + hoff);
    const uint4* vhp = (const uint4*)(vh_g + hoff);
    const uint4* vlp = (const uint4*)(vl_g + hoff);

    for (int jT = 0; jT <= iTile; ++jT) {
        const int j0 = jT * 64;
        __syncthreads();

        {
            const int base = j0 * 8;
            #pragma unroll
            for (int it = 0; it < 4; ++it) {
                int idx = it * 128 + tid;
                int r = idx >> 3, c8 = (idx & 7) * 8;
                *(uint4*)&sKh[r * KSTR + c8] = khp[base + idx];
                *(uint4*)&sKl[r * KSTR + c8] = klp[base + idx];
                *(uint4*)&sVh[r * KSTR + c8] = vhp[base + idx];
                *(uint4*)&sVl[r * KSTR + c8] = vlp[base + idx];
            }
        }
        __syncthreads();

        float s[8][4];
        #pragma unroll
        for (int ni = 0; ni < 8; ni++)
            #pragma unroll
            for (int e = 0; e < 4; e++) s[ni][e] = 0.f;

        #pragma unroll
        for (int kc = 0; kc < 4; ++kc) {
            #pragma unroll
            for (int n2 = 0; n2 < 4; ++n2) {
                unsigned rh[4], rl[4];
                const unsigned ad = (unsigned)((n2 * 16 + (lane & 15)) * KSTR2
                                               + (lane >> 4) * 16 + kc * 32);
                ldsm_x4(rh, bKh + ad);
                ldsm_x4(rl, bKl + ad);
                mma_bf16(s[2 * n2],     qhf[kc], rh[0], rh[2]);
                mma_bf16(s[2 * n2],     qhf[kc], rl[0], rl[2]);
                mma_bf16(s[2 * n2],     qlf[kc], rh[0], rh[2]);
                mma_bf16(s[2 * n2 + 1], qhf[kc], rh[1], rh[3]);
                mma_bf16(s[2 * n2 + 1], qhf[kc], rl[1], rl[3]);
                mma_bf16(s[2 * n2 + 1], qlf[kc], rh[1], rh[3]);
            }
        }

        if (jT == iTile) {
            const int row0 = i0 + wr + g, row1 = row0 + 8;
            #pragma unroll
            for (int ni = 0; ni < 8; ++ni) {
                const int c0 = j0 + ni * 8 + tq * 2;
                if (c0 > row0)     s[ni][0] = -INFINITY;
                if (c0 + 1 > row0) s[ni][1] = -INFINITY;
                if (c0 > row1)     s[ni][2] = -INFINITY;
                if (c0 + 1 > row1) s[ni][3] = -INFINITY;
            }
        }

        float rm0 = -INFINITY, rm1 = -INFINITY;
        #pragma unroll
        for (int ni = 0; ni < 8; ++ni) {
            rm0 = fmaxf(rm0, fmaxf(s[ni][0], s[ni][1]));
            rm1 = fmaxf(rm1, fmaxf(s[ni][2], s[ni][3]));
        }
        rm0 = fmaxf(rm0, __shfl_xor_sync(0xffffffffu, rm0, 1));
        rm0 = fmaxf(rm0, __shfl_xor_sync(0xffffffffu, rm0, 2));
        rm1 = fmaxf(rm1, __shfl_xor_sync(0xffffffffu, rm1, 1));
        rm1 = fmaxf(rm1, __shfl_xor_sync(0xffffffffu, rm1, 2));

        const float mn0 = fmaxf(m0, rm0), mn1 = fmaxf(m1, rm1);
        const float al0 = __expf(m0 - mn0), al1 = __expf(m1 - mn1);
        m0 = mn0; m1 = mn1;

        unsigned ph[8][2], pl[8][2];
        float sum0 = 0.f, sum1 = 0.f;
        #pragma unroll
        for (int ni = 0; ni < 8; ++ni) {
            float p0 = __expf(s[ni][0] - mn0);
            float p1 = __expf(s[ni][1] - mn0);
            float p2 = __expf(s[ni][2] - mn1);
            float p3 = __expf(s[ni][3] - mn1);
            sum0 += p0 + p1; sum1 += p2 + p3;
            split2(p0, p1, ph[ni][0], pl[ni][0]);
            split2(p2, p3, ph[ni][1], pl[ni][1]);
        }
        sum0 += __shfl_xor_sync(0xffffffffu, sum0, 1);
        sum0 += __shfl_xor_sync(0xffffffffu, sum0, 2);
        sum1 += __shfl_xor_sync(0xffffffffu, sum1, 1);
        sum1 += __shfl_xor_sync(0xffffffffu, sum1, 2);
        l0 = l0 * al0 + sum0;
        l1 = l1 * al1 + sum1;

        #pragma unroll
        for (int ni = 0; ni < 8; ++ni) {
            o[ni][0] *= al0; o[ni][1] *= al0;
            o[ni][2] *= al1; o[ni][3] *= al1;
        }

        #pragma unroll
        for (int kc = 0; kc < 4; ++kc) {
            unsigned ah[4]  = { ph[2 * kc][0], ph[2 * kc][1], ph[2 * kc + 1][0], ph[2 * kc + 1][1] };
            unsigned aml[4] = { pl[2 * kc][0], pl[2 * kc][1], pl[2 * kc + 1][0], pl[2 * kc + 1][1] };
            #pragma unroll
            for (int n2 = 0; n2 < 4; ++n2) {
                unsigned vh4[4], vl4[4];
                const unsigned ad = (unsigned)((kc * 16 + (lane & 15)) * KSTR2
                                               + (n2 * 2 + (lane >> 4)) * 16);
                ldsm_x4_t(vh4, bVh + ad);
                ldsm_x4_t(vl4, bVl + ad);
                mma_bf16(o[2 * n2],     ah,  vh4[0], vh4[1]);
                mma_bf16(o[2 * n2],     ah,  vl4[0], vl4[1]);
                mma_bf16(o[2 * n2],     aml, vh4[0], vh4[1]);
                mma_bf16(o[2 * n2 + 1], ah,  vh4[2], vh4[3]);
                mma_bf16(o[2 * n2 + 1], ah,  vl4[2], vl4[3]);
                mma_bf16(o[2 * n2 + 1], aml, vh4[2], vh4[3]);
            }
        }
    }

    // normalize + store as bf16 hi/lo
    const float inv0 = 1.f / l0, inv1 = 1.f / l1;
    const int row0 = i0 + wr + g;
    #pragma unroll
    for (int ni = 0; ni < 8; ++ni) {
        const int col = h * HD + ni * 8 + tq * 2;
        const size_t i0a = (size_t)(b * TT + row0) * CC + col;
        const size_t i1a = (size_t)(b * TT + row0 + 8) * CC + col;
        unsigned hh, ll;
        split2(o[ni][0] * inv0, o[ni][1] * inv0, hh, ll);
        *(unsigned*)(oh_g + i0a) = hh;
        *(unsigned*)(ol_g + i0a) = ll;
        split2(o[ni][2] * inv1, o[ni][3] * inv1, hh, ll);
        *(unsigned*)(oh_g + i1a) = hh;
        *(unsigned*)(ol_g + i1a) = ll;
    }
}

// ---------------------------------------------------------------------------
// Launch
// ---------------------------------------------------------------------------
extern "C" void kernel_launch(void* const* d_in, const int* in_sizes, int n_in,
                              void* d_out, int out_size)
{
    const float* x     = (const float*)d_in[0];
    const float* fcos  = (const float*)d_in[1];
    const float* fsin  = (const float*)d_in[2];
    const float* Wqkv  = (const float*)d_in[3];
    const float* bqkv  = (const float*)d_in[4];
    const float* Wproj = (const float*)d_in[5];
    const float* bproj = (const float*)d_in[6];
    float* out = (float*)d_out;

    float* qkv;
    __nv_bfloat16 *xh, *xl, *ath, *atl, *wqh, *wql, *wph, *wpl;
    __nv_bfloat16 *qh, *ql, *kh, *kl, *vh, *vl;
    cudaGetSymbolAddress((void**)&qkv, g_qkv);
    cudaGetSymbolAddress((void**)&xh, g_xh);   cudaGetSymbolAddress((void**)&xl, g_xl);
    cudaGetSymbolAddress((void**)&ath, g_ath); cudaGetSymbolAddress((void**)&atl, g_atl);
    cudaGetSymbolAddress((void**)&wqh, g_wqh); cudaGetSymbolAddress((void**)&wql, g_wql);
    cudaGetSymbolAddress((void**)&wph, g_wph); cudaGetSymbolAddress((void**)&wpl, g_wpl);
    cudaGetSymbolAddress((void**)&qh, g_qh);   cudaGetSymbolAddress((void**)&ql, g_ql);
    cudaGetSymbolAddress((void**)&kh, g_kh);   cudaGetSymbolAddress((void**)&kl, g_kl);
    cudaGetSymbolAddress((void**)&vh, g_vh);   cudaGetSymbolAddress((void**)&vl, g_vl);

    cudaFuncSetAttribute(bgemm2, cudaFuncAttributeMaxDynamicSharedMemorySize, GSMEM);

    // 0) prep: split x; transpose+split weights (constant work, small)
    convsplit<<<(MROWS * CC) / 1024, 256>>>(x, xh, xl);
    {
        dim3 g1(QKVW / 32, CC / 32);
        transpose_split<<<g1, 256>>>(Wqkv, wqh, wql, CC, QKVW);
        dim3 g2(CC / 32, CC / 32);
        transpose_split<<<g2, 256>>>(Wproj, wph, wpl, CC, CC);
    }

    // 1) QKV = x @ Wqkv + bqkv
    {
        dim3 grid(QKVW / 128, MROWS / 128);   // (24, 32)
        bgemm2<<<grid, 256, GSMEM>>>(xh, xl, wqh, wql, bqkv, qkv, MROWS, QKVW, CC);
    }
    // 2) RoPE + bf16 hi/lo split into head-contiguous layout
    rope_split<<<MROWS, 512>>>(qkv, fcos, fsin, qh, ql, kh, kl, vh, vl);

    // 3) Tensor-core causal flash attention -> bf16 hi/lo att
    {
        dim3 grid(TT / 64, BB * HH);
        attn_mma<<<grid, 128>>>(qh, ql, kh, kl, vh, vl, ath, atl);
    }
    // 4) out = att @ Wproj + bproj
    {
        dim3 grid(CC / 128, MROWS / 128);     // (8, 32)
        bgemm2<<<grid, 256, GSMEM>>>(ath, atl, wph, wpl, bproj, out, MROWS, CC, CC);
    }
}

// round 6
// speedup vs baseline: 1.6389x; 1.6389x over previous
#include <cuda_runtime.h>
#include <cuda_bf16.h>
#include <cuda_fp16.h>
#include <math.h>
#include <stdint.h>

// Problem constants
#define BB   2
#define TT   2048
#define CC   1024
#define HH   16
#define HD   64
#define HD2  32
#define MROWS (BB*TT)          // 4096
#define QKVW (3*CC)            // 3072

// Scratch (allocation-free rule: __device__ globals)
__device__ float g_qkv[(size_t)MROWS * QKVW];               // [B*T, 3C] fp32
// fp16 single-precision-emulation inputs for GEMMs
__device__ __half g_x16[(size_t)MROWS * CC];                // x as fp16 [M][K]
__device__ __half g_o16[(size_t)MROWS * CC];                // attention out fp16 [M][K]
__device__ __half g_wq16[(size_t)QKVW * CC];                // Wqkv^T fp16 [N][K]
__device__ __half g_wp16[(size_t)CC * CC];                  // Wproj^T fp16 [N][K]
// Head-contiguous bf16 hi/lo splits of roped q, k and v: [b*H+h][T][64]
#define HELEMS ((size_t)BB * HH * TT * HD)
__device__ __nv_bfloat16 g_qh[HELEMS], g_ql[HELEMS];
__device__ __nv_bfloat16 g_kh[HELEMS], g_kl[HELEMS];
__device__ __nv_bfloat16 g_vh[HELEMS], g_vl[HELEMS];

// ---------------------------------------------------------------------------
// Helpers
// ---------------------------------------------------------------------------
__device__ __forceinline__ void split2(float x, float y, unsigned &h, unsigned &l)
{
    __nv_bfloat16 hx = __float2bfloat16(x), hy = __float2bfloat16(y);
    float rx = x - __bfloat162float(hx);
    float ry = y - __bfloat162float(hy);
    __nv_bfloat16 lx = __float2bfloat16(rx), ly = __float2bfloat16(ry);
    h = (unsigned)*(unsigned short*)&hx | ((unsigned)*(unsigned short*)&hy << 16);
    l = (unsigned)*(unsigned short*)&lx | ((unsigned)*(unsigned short*)&ly << 16);
}

__device__ __forceinline__ void split1(float x, __nv_bfloat16 &h, __nv_bfloat16 &l)
{
    h = __float2bfloat16(x);
    l = __float2bfloat16(x - __bfloat162float(h));
}

__device__ __forceinline__ void ldsm_x4(unsigned r[4], unsigned addr)
{
    asm volatile("ldmatrix.sync.aligned.m8n8.x4.shared.b16 {%0,%1,%2,%3}, [%4];"
                 : "=r"(r[0]), "=r"(r[1]), "=r"(r[2]), "=r"(r[3]) : "r"(addr));
}

__device__ __forceinline__ void ldsm_x4_t(unsigned r[4], unsigned addr)
{
    asm volatile("ldmatrix.sync.aligned.m8n8.x4.trans.shared.b16 {%0,%1,%2,%3}, [%4];"
                 : "=r"(r[0]), "=r"(r[1]), "=r"(r[2]), "=r"(r[3]) : "r"(addr));
}

__device__ __forceinline__ void mma_bf16(float d[4], const unsigned a[4], unsigned b0, unsigned b1)
{
    asm volatile("mma.sync.aligned.m16n8k16.row.col.f32.bf16.bf16.f32 "
                 "{%0,%1,%2,%3}, {%4,%5,%6,%7}, {%8,%9}, {%0,%1,%2,%3};"
                 : "+f"(d[0]), "+f"(d[1]), "+f"(d[2]), "+f"(d[3])
                 : "r"(a[0]), "r"(a[1]), "r"(a[2]), "r"(a[3]), "r"(b0), "r"(b1));
}

__device__ __forceinline__ void mma_fp16(float d[4], const unsigned a[4], unsigned b0, unsigned b1)
{
    asm volatile("mma.sync.aligned.m16n8k16.row.col.f32.f16.f16.f32 "
                 "{%0,%1,%2,%3}, {%4,%5,%6,%7}, {%8,%9}, {%0,%1,%2,%3};"
                 : "+f"(d[0]), "+f"(d[1]), "+f"(d[2]), "+f"(d[3])
                 : "r"(a[0]), "r"(a[1]), "r"(a[2]), "r"(a[3]), "r"(b0), "r"(b1));
}

__device__ __forceinline__ void cp16(unsigned dst, const void* src)
{
    asm volatile("cp.async.cg.shared.global [%0], [%1], 16;" :: "r"(dst), "l"(src));
}
#define CP_COMMIT  asm volatile("cp.async.commit_group;" ::: "memory")
#define CP_WAIT(n) asm volatile("cp.async.wait_group %0;" :: "n"(n) : "memory")

// ---------------------------------------------------------------------------
// Prep kernels
// ---------------------------------------------------------------------------
// fp32 -> fp16 elementwise (x)
__global__ __launch_bounds__(256) void convhalf(
    const float* __restrict__ X, __half* __restrict__ X16)
{
    int i = (blockIdx.x * 256 + threadIdx.x) * 4;
    float4 v = *(const float4*)(X + i);
    __half2 a = __floats2half2_rn(v.x, v.y);
    __half2 b = __floats2half2_rn(v.z, v.w);
    *(uint2*)(X16 + i) = make_uint2(*(unsigned*)&a, *(unsigned*)&b);
}

// W [K][N] fp32 -> Wt fp16 [N][K]  (32x32 smem tile transpose)
__global__ __launch_bounds__(256) void transpose_half(
    const float* __restrict__ W, __half* __restrict__ Wt, int K, int N)
{
    __shared__ float tile[32][33];
    const int n0 = blockIdx.x * 32, k0 = blockIdx.y * 32;
    const int tx = threadIdx.x & 31, ty = threadIdx.x >> 5;   // 32 x 8
    #pragma unroll
    for (int i = 0; i < 32; i += 8)
        tile[ty + i][tx] = W[(size_t)(k0 + ty + i) * N + n0 + tx];
    __syncthreads();
    #pragma unroll
    for (int i = 0; i < 32; i += 8)
        Wt[(size_t)(n0 + ty + i) * K + k0 + tx] = __float2half_rn(tile[tx][ty + i]);
}

// ---------------------------------------------------------------------------
// Single-pass fp16 mma.sync GEMM:
//   C[M,N] = A@W^T + bias;  A fp16 [M][K] k-major; W fp16 [N][K] k-major.
// CTA tile 128x128, BK=32, 256 threads (8 warps as 2x4, warp tile 64x32).
// cp.async double-buffered smem; 80B padded rows (16B aligned, ldmatrix
// conflict-free: 80*r mod 128 hits all 8 offsets over r=0..7).
// ---------------------------------------------------------------------------
#define GROW   80                     // bytes per smem row (32 fp16 = 64B + pad)
#define GMAT   (128*GROW)             // 10240 B per matrix
#define GSTAGE (2*GMAT)               // A, B
#define GSMEM  (2*GSTAGE)             // 40960 B

__device__ __forceinline__ void h_fill(
    unsigned sb,
    const __half* __restrict__ A_g, const __half* __restrict__ B_g,
    int row0, int col0, int K, int kbase, int tid)
{
    #pragma unroll
    for (int it = 0; it < 2; ++it) {
        int idx = it * 256 + tid;          // 0..511
        int r = idx >> 2;                  // 0..127
        int c = idx & 3;                   // 16B chunk
        unsigned doff = (unsigned)(r * GROW + c * 16);
        cp16(sb + doff,        A_g + (size_t)(row0 + r) * K + kbase + c * 8);
        cp16(sb + GMAT + doff, B_g + (size_t)(col0 + r) * K + kbase + c * 8);
    }
}

__global__ __launch_bounds__(256) void hgemm(
    const __half* __restrict__ A_g, const __half* __restrict__ B_g,
    const float* __restrict__ bias, float* __restrict__ Cm,
    int M, int N, int K)
{
    extern __shared__ __align__(16) char smem[];
    const unsigned sb0 = (unsigned)__cvta_generic_to_shared(smem);

    const int tid  = threadIdx.x;
    const int lane = tid & 31;
    const int wid  = tid >> 5;
    const int wm   = wid >> 2;          // 0..1
    const int wn   = wid & 3;           // 0..3
    const int row0 = blockIdx.y * 128;
    const int col0 = blockIdx.x * 128;

    float acc[4][4][4];
    #pragma unroll
    for (int mi = 0; mi < 4; mi++)
        #pragma unroll
        for (int ni = 0; ni < 4; ni++)
            #pragma unroll
            for (int e = 0; e < 4; e++) acc[mi][ni][e] = 0.f;

    const int KT = K >> 5;              // 32-wide chunks

    h_fill(sb0, A_g, B_g, row0, col0, K, 0, tid);
    CP_COMMIT;

    const unsigned aoff = (unsigned)((wm * 64 + (lane & 15)) * GROW + (lane >> 4) * 16);
    const unsigned boff = (unsigned)(GMAT + (wn * 32 + (lane & 15)) * GROW + (lane >> 4) * 16);

    for (int kt = 0; kt < KT; ++kt) {
        const unsigned sb = sb0 + (unsigned)(kt & 1) * GSTAGE;

        if (kt + 1 < KT) {
            h_fill(sb0 + (unsigned)((kt + 1) & 1) * GSTAGE,
                   A_g, B_g, row0, col0, K, (kt + 1) * 32, tid);
            CP_COMMIT;
            CP_WAIT(1);
        } else {
            CP_WAIT(0);
        }
        __syncthreads();

        #pragma unroll
        for (int kc = 0; kc < 2; ++kc) {
            unsigned af[4][4], bf[2][4];
            #pragma unroll
            for (int n2 = 0; n2 < 2; ++n2)
                ldsm_x4(bf[n2], sb + boff + n2 * 16 * GROW + kc * 32);
            #pragma unroll
            for (int mi = 0; mi < 4; ++mi)
                ldsm_x4(af[mi], sb + aoff + mi * 16 * GROW + kc * 32);
            #pragma unroll
            for (int mi = 0; mi < 4; ++mi)
                #pragma unroll
                for (int n2 = 0; n2 < 2; ++n2) {
                    mma_fp16(acc[mi][2 * n2],     af[mi], bf[n2][0], bf[n2][2]);
                    mma_fp16(acc[mi][2 * n2 + 1], af[mi], bf[n2][1], bf[n2][3]);
                }
        }
        __syncthreads();
    }

    const int g  = lane >> 2;
    const int tq = lane & 3;
    #pragma unroll
    for (int mi = 0; mi < 4; mi++) {
        const int r0 = row0 + wm * 64 + mi * 16 + g;
        #pragma unroll
        for (int ni = 0; ni < 4; ni++) {
            const int c = col0 + wn * 32 + (ni >> 1) * 16 + (ni & 1) * 8 + tq * 2;
            const float bz0 = bias[c], bz1 = bias[c + 1];
            *(float2*)(Cm + (size_t)r0 * N + c) =
                make_float2(acc[mi][ni][0] + bz0, acc[mi][ni][1] + bz1);
            *(float2*)(Cm + (size_t)(r0 + 8) * N + c) =
                make_float2(acc[mi][ni][2] + bz0, acc[mi][ni][3] + bz1);
        }
    }
}

// ---------------------------------------------------------------------------
// RoPE + split to bf16 hi/lo, head-contiguous layout [b*H+h][T][64].
// ---------------------------------------------------------------------------
__global__ __launch_bounds__(512) void rope_split(
    const float* __restrict__ qkv,
    const float* __restrict__ cosf, const float* __restrict__ sinf,
    __nv_bfloat16* __restrict__ qh, __nv_bfloat16* __restrict__ ql,
    __nv_bfloat16* __restrict__ kh, __nv_bfloat16* __restrict__ kl,
    __nv_bfloat16* __restrict__ vh, __nv_bfloat16* __restrict__ vl)
{
    const int bt  = blockIdx.x;
    const int b   = bt / TT;
    const int t   = bt % TT;
    const int tid = threadIdx.x;
    const int h   = tid >> 5;
    const int d   = tid & 31;

    const float c = cosf[t * HD2 + d];
    const float s = sinf[t * HD2 + d];

    const float* base = qkv + (size_t)bt * QKVW;
    const size_t dst = ((size_t)(b * HH + h) * TT + t) * HD + d;

    float q1 = base[h * HD + d], q2 = base[h * HD + d + HD2];
    float qr1 = (q1 * c - q2 * s) * 0.125f;
    float qr2 = (q1 * s + q2 * c) * 0.125f;
    split1(qr1, qh[dst], ql[dst]);
    split1(qr2, qh[dst + HD2], ql[dst + HD2]);

    float k1 = base[CC + h * HD + d], k2 = base[CC + h * HD + d + HD2];
    float kr1 = k1 * c - k2 * s;
    float kr2 = k1 * s + k2 * c;
    split1(kr1, kh[dst], kl[dst]);
    split1(kr2, kh[dst + HD2], kl[dst + HD2]);

    float v1 = base[2 * CC + h * HD + d], v2 = base[2 * CC + h * HD + d + HD2];
    split1(v1, vh[dst], vl[dst]);
    split1(v2, vh[dst + HD2], vl[dst + HD2]);
}

// ---------------------------------------------------------------------------
// Tensor-core flash attention (split-bf16, causal). Output: fp16 [B*T][C].
// Br=64 (4 warps x 16 rows), Bc=64. grid=(T/64, B*H), 128 threads.
// ---------------------------------------------------------------------------
#define KSTR  72
#define KSTR2 144

__global__ __launch_bounds__(128) void attn_mma(
    const __nv_bfloat16* __restrict__ qh_g, const __nv_bfloat16* __restrict__ ql_g,
    const __nv_bfloat16* __restrict__ kh_g, const __nv_bfloat16* __restrict__ kl_g,
    const __nv_bfloat16* __restrict__ vh_g, const __nv_bfloat16* __restrict__ vl_g,
    __half* __restrict__ o16_g)
{
    __shared__ __align__(16) __nv_bfloat16 sKh[64 * KSTR];
    __shared__ __align__(16) __nv_bfloat16 sKl[64 * KSTR];
    __shared__ __align__(16) __nv_bfloat16 sVh[64 * KSTR];
    __shared__ __align__(16) __nv_bfloat16 sVl[64 * KSTR];

    const int iTile = gridDim.x - 1 - blockIdx.x;   // heavy tiles first
    const int bh    = blockIdx.y;
    const int b = bh / HH, h = bh % HH;
    const int tid  = threadIdx.x;
    const int lane = tid & 31;
    const int wid  = tid >> 5;
    const int wr   = wid * 16;
    const int i0   = iTile * 64;
    const int g    = lane >> 2;
    const int tq   = lane & 3;

    const size_t hoff = (size_t)bh * TT * HD;

    const unsigned bKh = (unsigned)__cvta_generic_to_shared(sKh);
    const unsigned bKl = (unsigned)__cvta_generic_to_shared(sKl);
    const unsigned bVh = (unsigned)__cvta_generic_to_shared(sVh);
    const unsigned bVl = (unsigned)__cvta_generic_to_shared(sVl);

    {
        const uint4* qhp = (const uint4*)(qh_g + hoff + (size_t)i0 * HD);
        const uint4* qlp = (const uint4*)(ql_g + hoff + (size_t)i0 * HD);
        #pragma unroll
        for (int it = 0; it < 4; ++it) {
            int idx = it * 128 + tid;
            int r = idx >> 3, c8 = (idx & 7) * 8;
            *(uint4*)&sKh[r * KSTR + c8] = qhp[idx];
            *(uint4*)&sKl[r * KSTR + c8] = qlp[idx];
        }
    }
    __syncthreads();

    unsigned qhf[4][4], qlf[4][4];
    {
        const unsigned aoffq = (unsigned)((wr + (lane & 15)) * KSTR2 + (lane >> 4) * 16);
        #pragma unroll
        for (int kc = 0; kc < 4; ++kc) {
            ldsm_x4(qhf[kc], bKh + aoffq + kc * 32);
            ldsm_x4(qlf[kc], bKl + aoffq + kc * 32);
        }
    }

    float m0 = -INFINITY, m1 = -INFINITY, l0 = 0.f, l1 = 0.f;
    float o[8][4];
    #pragma unroll
    for (int ni = 0; ni < 8; ni++)
        #pragma unroll
        for (int e = 0; e < 4; e++) o[ni][e] = 0.f;

    const uint4* khp = (const uint4*)(kh_g + hoff);
    const uint4* klp = (const uint4*)(kl_g + hoff);
    const uint4* vhp = (const uint4*)(vh_g + hoff);
    const uint4* vlp = (const uint4*)(vl_g + hoff);

    for (int jT = 0; jT <= iTile; ++jT) {
        const int j0 = jT * 64;
        __syncthreads();

        {
            const int base = j0 * 8;
            #pragma unroll
            for (int it = 0; it < 4; ++it) {
                int idx = it * 128 + tid;
                int r = idx >> 3, c8 = (idx & 7) * 8;
                *(uint4*)&sKh[r * KSTR + c8] = khp[base + idx];
                *(uint4*)&sKl[r * KSTR + c8] = klp[base + idx];
                *(uint4*)&sVh[r * KSTR + c8] = vhp[base + idx];
                *(uint4*)&sVl[r * KSTR + c8] = vlp[base + idx];
            }
        }
        __syncthreads();

        float s[8][4];
        #pragma unroll
        for (int ni = 0; ni < 8; ni++)
            #pragma unroll
            for (int e = 0; e < 4; e++) s[ni][e] = 0.f;

        #pragma unroll
        for (int kc = 0; kc < 4; ++kc) {
            #pragma unroll
            for (int n2 = 0; n2 < 4; ++n2) {
                unsigned rh[4], rl[4];
                const unsigned ad = (unsigned)((n2 * 16 + (lane & 15)) * KSTR2
                                               + (lane >> 4) * 16 + kc * 32);
                ldsm_x4(rh, bKh + ad);
                ldsm_x4(rl, bKl + ad);
                mma_bf16(s[2 * n2],     qhf[kc], rh[0], rh[2]);
                mma_bf16(s[2 * n2],     qhf[kc], rl[0], rl[2]);
                mma_bf16(s[2 * n2],     qlf[kc], rh[0], rh[2]);
                mma_bf16(s[2 * n2 + 1], qhf[kc], rh[1], rh[3]);
                mma_bf16(s[2 * n2 + 1], qhf[kc], rl[1], rl[3]);
                mma_bf16(s[2 * n2 + 1], qlf[kc], rh[1], rh[3]);
            }
        }

        if (jT == iTile) {
            const int row0 = i0 + wr + g, row1 = row0 + 8;
            #pragma unroll
            for (int ni = 0; ni < 8; ++ni) {
                const int c0 = j0 + ni * 8 + tq * 2;
                if (c0 > row0)     s[ni][0] = -INFINITY;
                if (c0 + 1 > row0) s[ni][1] = -INFINITY;
                if (c0 > row1)     s[ni][2] = -INFINITY;
                if (c0 + 1 > row1) s[ni][3] = -INFINITY;
            }
        }

        float rm0 = -INFINITY, rm1 = -INFINITY;
        #pragma unroll
        for (int ni = 0; ni < 8; ++ni) {
            rm0 = fmaxf(rm0, fmaxf(s[ni][0], s[ni][1]));
            rm1 = fmaxf(rm1, fmaxf(s[ni][2], s[ni][3]));
        }
        rm0 = fmaxf(rm0, __shfl_xor_sync(0xffffffffu, rm0, 1));
        rm0 = fmaxf(rm0, __shfl_xor_sync(0xffffffffu, rm0, 2));
        rm1 = fmaxf(rm1, __shfl_xor_sync(0xffffffffu, rm1, 1));
        rm1 = fmaxf(rm1, __shfl_xor_sync(0xffffffffu, rm1, 2));

        const float mn0 = fmaxf(m0, rm0), mn1 = fmaxf(m1, rm1);
        const float al0 = __expf(m0 - mn0), al1 = __expf(m1 - mn1);
        m0 = mn0; m1 = mn1;

        unsigned ph[8][2], pl[8][2];
        float sum0 = 0.f, sum1 = 0.f;
        #pragma unroll
        for (int ni = 0; ni < 8; ++ni) {
            float p0 = __expf(s[ni][0] - mn0);
            float p1 = __expf(s[ni][1] - mn0);
            float p2 = __expf(s[ni][2] - mn1);
            float p3 = __expf(s[ni][3] - mn1);
            sum0 += p0 + p1; sum1 += p2 + p3;
            split2(p0, p1, ph[ni][0], pl[ni][0]);
            split2(p2, p3, ph[ni][1], pl[ni][1]);
        }
        sum0 += __shfl_xor_sync(0xffffffffu, sum0, 1);
        sum0 += __shfl_xor_sync(0xffffffffu, sum0, 2);
        sum1 += __shfl_xor_sync(0xffffffffu, sum1, 1);
        sum1 += __shfl_xor_sync(0xffffffffu, sum1, 2);
        l0 = l0 * al0 + sum0;
        l1 = l1 * al1 + sum1;

        #pragma unroll
        for (int ni = 0; ni < 8; ++ni) {
            o[ni][0] *= al0; o[ni][1] *= al0;
            o[ni][2] *= al1; o[ni][3] *= al1;
        }

        #pragma unroll
        for (int kc = 0; kc < 4; ++kc) {
            unsigned ah[4]  = { ph[2 * kc][0], ph[2 * kc][1], ph[2 * kc + 1][0], ph[2 * kc + 1][1] };
            unsigned aml[4] = { pl[2 * kc][0], pl[2 * kc][1], pl[2 * kc + 1][0], pl[2 * kc + 1][1] };
            #pragma unroll
            for (int n2 = 0; n2 < 4; ++n2) {
                unsigned vh4[4], vl4[4];
                const unsigned ad = (unsigned)((kc * 16 + (lane & 15)) * KSTR2
                                               + (n2 * 2 + (lane >> 4)) * 16);
                ldsm_x4_t(vh4, bVh + ad);
                ldsm_x4_t(vl4, bVl + ad);
                mma_bf16(o[2 * n2],     ah,  vh4[0], vh4[1]);
                mma_bf16(o[2 * n2],     ah,  vl4[0], vl4[1]);
                mma_bf16(o[2 * n2],     aml, vh4[0], vh4[1]);
                mma_bf16(o[2 * n2 + 1], ah,  vh4[2], vh4[3]);
                mma_bf16(o[2 * n2 + 1], ah,  vl4[2], vl4[3]);
                mma_bf16(o[2 * n2 + 1], aml, vh4[2], vh4[3]);
            }
        }
    }

    // normalize + store as fp16 (input to proj hgemm)
    const float inv0 = 1.f / l0, inv1 = 1.f / l1;
    const int row0 = i0 + wr + g;
    #pragma unroll
    for (int ni = 0; ni < 8; ++ni) {
        const int col = h * HD + ni * 8 + tq * 2;
        const size_t i0a = (size_t)(b * TT + row0) * CC + col;
        const size_t i1a = (size_t)(b * TT + row0 + 8) * CC + col;
        __half2 v0 = __floats2half2_rn(o[ni][0] * inv0, o[ni][1] * inv0);
        __half2 v1 = __floats2half2_rn(o[ni][2] * inv1, o[ni][3] * inv1);
        *(__half2*)(o16_g + i0a) = v0;
        *(__half2*)(o16_g + i1a) = v1;
    }
}

// ---------------------------------------------------------------------------
// Launch
// ---------------------------------------------------------------------------
extern "C" void kernel_launch(void* const* d_in, const int* in_sizes, int n_in,
                              void* d_out, int out_size)
{
    const float* x     = (const float*)d_in[0];
    const float* fcos  = (const float*)d_in[1];
    const float* fsin  = (const float*)d_in[2];
    const float* Wqkv  = (const float*)d_in[3];
    const float* bqkv  = (const float*)d_in[4];
    const float* Wproj = (const float*)d_in[5];
    const float* bproj = (const float*)d_in[6];
    float* out = (float*)d_out;

    float* qkv;
    __half *x16, *o16, *wq16, *wp16;
    __nv_bfloat16 *qh, *ql, *kh, *kl, *vh, *vl;
    cudaGetSymbolAddress((void**)&qkv, g_qkv);
    cudaGetSymbolAddress((void**)&x16, g_x16);
    cudaGetSymbolAddress((void**)&o16, g_o16);
    cudaGetSymbolAddress((void**)&wq16, g_wq16);
    cudaGetSymbolAddress((void**)&wp16, g_wp16);
    cudaGetSymbolAddress((void**)&qh, g_qh);   cudaGetSymbolAddress((void**)&ql, g_ql);
    cudaGetSymbolAddress((void**)&kh, g_kh);   cudaGetSymbolAddress((void**)&kl, g_kl);
    cudaGetSymbolAddress((void**)&vh, g_vh);   cudaGetSymbolAddress((void**)&vl, g_vl);

    cudaFuncSetAttribute(hgemm, cudaFuncAttributeMaxDynamicSharedMemorySize, GSMEM);

    // 0) prep: x -> fp16; W -> W^T fp16
    convhalf<<<(MROWS * CC) / 1024, 256>>>(x, x16);
    {
        dim3 g1(QKVW / 32, CC / 32);
        transpose_half<<<g1, 256>>>(Wqkv, wq16, CC, QKVW);
        dim3 g2(CC / 32, CC / 32);
        transpose_half<<<g2, 256>>>(Wproj, wp16, CC, CC);
    }

    // 1) QKV = x @ Wqkv + bqkv  (single-pass fp16)
    {
        dim3 grid(QKVW / 128, MROWS / 128);   // (24, 32)
        hgemm<<<grid, 256, GSMEM>>>(x16, wq16, bqkv, qkv, MROWS, QKVW, CC);
    }
    // 2) RoPE + bf16 hi/lo split into head-contiguous layout
    rope_split<<<MROWS, 512>>>(qkv, fcos, fsin, qh, ql, kh, kl, vh, vl);

    // 3) Tensor-core causal flash attention (split-bf16) -> fp16 att
    {
        dim3 grid(TT / 64, BB * HH);
        attn_mma<<<grid, 128>>>(qh, ql, kh, kl, vh, vl, o16);
    }
    // 4) out = att @ Wproj + bproj  (single-pass fp16)
    {
        dim3 grid(CC / 128, MROWS / 128);     // (8, 32)
        hgemm<<<grid, 256, GSMEM>>>(o16, wp16, bproj, out, MROWS, CC, CC);
    }
}

// round 7
// speedup vs baseline: 1.8176x; 1.1090x over previous
#include <cuda_runtime.h>
#include <cuda_bf16.h>
#include <cuda_fp16.h>
#include <math.h>
#include <stdint.h>

// Problem constants
#define BB   2
#define TT   2048
#define CC   1024
#define HH   16
#define HD   64
#define HD2  32
#define MROWS (BB*TT)          // 4096
#define QKVW (3*CC)            // 3072

// Scratch (allocation-free rule: __device__ globals)
__device__ float g_qkv[(size_t)MROWS * QKVW];               // [B*T, 3C] fp32
__device__ __half g_x16[(size_t)MROWS * CC];                // x fp16 [M][K]
__device__ __half g_o16[(size_t)MROWS * CC];                // attention out fp16 [M][K]
__device__ __half g_wq16[(size_t)QKVW * CC];                // Wqkv^T fp16 [N][K]
__device__ __half g_wp16[(size_t)CC * CC];                  // Wproj^T fp16 [N][K]
// Head-contiguous q/k bf16 hi/lo + v fp16: [b*H+h][T][64]
#define HELEMS ((size_t)BB * HH * TT * HD)
__device__ __nv_bfloat16 g_qh[HELEMS], g_ql[HELEMS];
__device__ __nv_bfloat16 g_kh[HELEMS], g_kl[HELEMS];
__device__ __half        g_v16[HELEMS];

// ---------------------------------------------------------------------------
// Helpers
// ---------------------------------------------------------------------------
__device__ __forceinline__ void split1(float x, __nv_bfloat16 &h, __nv_bfloat16 &l)
{
    h = __float2bfloat16(x);
    l = __float2bfloat16(x - __bfloat162float(h));
}

__device__ __forceinline__ void ldsm_x4(unsigned r[4], unsigned addr)
{
    asm volatile("ldmatrix.sync.aligned.m8n8.x4.shared.b16 {%0,%1,%2,%3}, [%4];"
                 : "=r"(r[0]), "=r"(r[1]), "=r"(r[2]), "=r"(r[3]) : "r"(addr));
}

__device__ __forceinline__ void ldsm_x4_t(unsigned r[4], unsigned addr)
{
    asm volatile("ldmatrix.sync.aligned.m8n8.x4.trans.shared.b16 {%0,%1,%2,%3}, [%4];"
                 : "=r"(r[0]), "=r"(r[1]), "=r"(r[2]), "=r"(r[3]) : "r"(addr));
}

__device__ __forceinline__ void mma_bf16(float d[4], const unsigned a[4], unsigned b0, unsigned b1)
{
    asm volatile("mma.sync.aligned.m16n8k16.row.col.f32.bf16.bf16.f32 "
                 "{%0,%1,%2,%3}, {%4,%5,%6,%7}, {%8,%9}, {%0,%1,%2,%3};"
                 : "+f"(d[0]), "+f"(d[1]), "+f"(d[2]), "+f"(d[3])
                 : "r"(a[0]), "r"(a[1]), "r"(a[2]), "r"(a[3]), "r"(b0), "r"(b1));
}

__device__ __forceinline__ void mma_fp16(float d[4], const unsigned a[4], unsigned b0, unsigned b1)
{
    asm volatile("mma.sync.aligned.m16n8k16.row.col.f32.f16.f16.f32 "
                 "{%0,%1,%2,%3}, {%4,%5,%6,%7}, {%8,%9}, {%0,%1,%2,%3};"
                 : "+f"(d[0]), "+f"(d[1]), "+f"(d[2]), "+f"(d[3])
                 : "r"(a[0]), "r"(a[1]), "r"(a[2]), "r"(a[3]), "r"(b0), "r"(b1));
}

__device__ __forceinline__ void cp16(unsigned dst, const void* src)
{
    asm volatile("cp.async.cg.shared.global [%0], [%1], 16;" :: "r"(dst), "l"(src));
}
#define CP_COMMIT  asm volatile("cp.async.commit_group;" ::: "memory")
#define CP_WAIT(n) asm volatile("cp.async.wait_group %0;" :: "n"(n) : "memory")

// ---------------------------------------------------------------------------
// Prep kernels
// ---------------------------------------------------------------------------
__global__ __launch_bounds__(256) void convhalf(
    const float* __restrict__ X, __half* __restrict__ X16)
{
    int i = (blockIdx.x * 256 + threadIdx.x) * 4;
    float4 v = *(const float4*)(X + i);
    __half2 a = __floats2half2_rn(v.x, v.y);
    __half2 b = __floats2half2_rn(v.z, v.w);
    *(uint2*)(X16 + i) = make_uint2(*(unsigned*)&a, *(unsigned*)&b);
}

__global__ __launch_bounds__(256) void transpose_half(
    const float* __restrict__ W, __half* __restrict__ Wt, int K, int N)
{
    __shared__ float tile[32][33];
    const int n0 = blockIdx.x * 32, k0 = blockIdx.y * 32;
    const int tx = threadIdx.x & 31, ty = threadIdx.x >> 5;
    #pragma unroll
    for (int i = 0; i < 32; i += 8)
        tile[ty + i][tx] = W[(size_t)(k0 + ty + i) * N + n0 + tx];
    __syncthreads();
    #pragma unroll
    for (int i = 0; i < 32; i += 8)
        Wt[(size_t)(n0 + ty + i) * K + k0 + tx] = __float2half_rn(tile[tx][ty + i]);
}

// ---------------------------------------------------------------------------
// Single-pass fp16 GEMM, 4-stage cp.async ring:
//   C[M,N] = A@W^T + bias;  A fp16 [M][K]; W fp16 [N][K].
// CTA 128x128, BK=32, 256 threads (8 warps 2x4, warp tile 64x32).
// ---------------------------------------------------------------------------
#define GROW   80
#define GMAT   (128*GROW)             // 10240
#define GSTAGE (2*GMAT)               // 20480
#define GSMEM  (4*GSTAGE)             // 81920

__device__ __forceinline__ void h_fill(
    unsigned sb,
    const __half* __restrict__ A_g, const __half* __restrict__ B_g,
    int row0, int col0, int K, int kbase, int tid)
{
    #pragma unroll
    for (int it = 0; it < 2; ++it) {
        int idx = it * 256 + tid;
        int r = idx >> 2;
        int c = idx & 3;
        unsigned doff = (unsigned)(r * GROW + c * 16);
        cp16(sb + doff,        A_g + (size_t)(row0 + r) * K + kbase + c * 8);
        cp16(sb + GMAT + doff, B_g + (size_t)(col0 + r) * K + kbase + c * 8);
    }
}

__global__ __launch_bounds__(256) void hgemm(
    const __half* __restrict__ A_g, const __half* __restrict__ B_g,
    const float* __restrict__ bias, float* __restrict__ Cm,
    int M, int N, int K)
{
    extern __shared__ __align__(16) char smem[];
    const unsigned sb0 = (unsigned)__cvta_generic_to_shared(smem);

    const int tid  = threadIdx.x;
    const int lane = tid & 31;
    const int wid  = tid >> 5;
    const int wm   = wid >> 2;
    const int wn   = wid & 3;
    const int row0 = blockIdx.y * 128;
    const int col0 = blockIdx.x * 128;

    float acc[4][4][4];
    #pragma unroll
    for (int mi = 0; mi < 4; mi++)
        #pragma unroll
        for (int ni = 0; ni < 4; ni++)
            #pragma unroll
            for (int e = 0; e < 4; e++) acc[mi][ni][e] = 0.f;

    const int KT = K >> 5;

    // prologue: fill stages 0..2
    h_fill(sb0,              A_g, B_g, row0, col0, K, 0,  tid); CP_COMMIT;
    h_fill(sb0 + GSTAGE,     A_g, B_g, row0, col0, K, 32, tid); CP_COMMIT;
    h_fill(sb0 + 2 * GSTAGE, A_g, B_g, row0, col0, K, 64, tid); CP_COMMIT;

    const unsigned aoff = (unsigned)((wm * 64 + (lane & 15)) * GROW + (lane >> 4) * 16);
    const unsigned boff = (unsigned)(GMAT + (wn * 32 + (lane & 15)) * GROW + (lane >> 4) * 16);

    for (int kt = 0; kt < KT; ++kt) {
        const unsigned sb = sb0 + (unsigned)(kt & 3) * GSTAGE;

        const int rem = KT - 1 - kt;
        if (rem >= 2)      CP_WAIT(2);
        else if (rem == 1) CP_WAIT(1);
        else               CP_WAIT(0);
        __syncthreads();   // stage kt ready everywhere; all warps done with stage kt-1

        if (kt + 3 < KT) {
            h_fill(sb0 + (unsigned)((kt + 3) & 3) * GSTAGE,
                   A_g, B_g, row0, col0, K, (kt + 3) * 32, tid);
            CP_COMMIT;
        }

        #pragma unroll
        for (int kc = 0; kc < 2; ++kc) {
            unsigned af[4][4], bf[2][4];
            #pragma unroll
            for (int n2 = 0; n2 < 2; ++n2)
                ldsm_x4(bf[n2], sb + boff + n2 * 16 * GROW + kc * 32);
            #pragma unroll
            for (int mi = 0; mi < 4; ++mi)
                ldsm_x4(af[mi], sb + aoff + mi * 16 * GROW + kc * 32);
            #pragma unroll
            for (int mi = 0; mi < 4; ++mi)
                #pragma unroll
                for (int n2 = 0; n2 < 2; ++n2) {
                    mma_fp16(acc[mi][2 * n2],     af[mi], bf[n2][0], bf[n2][2]);
                    mma_fp16(acc[mi][2 * n2 + 1], af[mi], bf[n2][1], bf[n2][3]);
                }
        }
    }

    const int g  = lane >> 2;
    const int tq = lane & 3;
    #pragma unroll
    for (int mi = 0; mi < 4; mi++) {
        const int r0 = row0 + wm * 64 + mi * 16 + g;
        #pragma unroll
        for (int ni = 0; ni < 4; ni++) {
            const int c = col0 + wn * 32 + (ni >> 1) * 16 + (ni & 1) * 8 + tq * 2;
            const float bz0 = bias[c], bz1 = bias[c + 1];
            *(float2*)(Cm + (size_t)r0 * N + c) =
                make_float2(acc[mi][ni][0] + bz0, acc[mi][ni][1] + bz1);
            *(float2*)(Cm + (size_t)(r0 + 8) * N + c) =
                make_float2(acc[mi][ni][2] + bz0, acc[mi][ni][3] + bz1);
        }
    }
}

// ---------------------------------------------------------------------------
// RoPE: q,k -> bf16 hi/lo; v -> fp16. Head-contiguous [b*H+h][T][64].
// ---------------------------------------------------------------------------
__global__ __launch_bounds__(512) void rope_split(
    const float* __restrict__ qkv,
    const float* __restrict__ cosf, const float* __restrict__ sinf,
    __nv_bfloat16* __restrict__ qh, __nv_bfloat16* __restrict__ ql,
    __nv_bfloat16* __restrict__ kh, __nv_bfloat16* __restrict__ kl,
    __half* __restrict__ v16)
{
    const int bt  = blockIdx.x;
    const int b   = bt / TT;
    const int t   = bt % TT;
    const int tid = threadIdx.x;
    const int h   = tid >> 5;
    const int d   = tid & 31;

    const float c = cosf[t * HD2 + d];
    const float s = sinf[t * HD2 + d];

    const float* base = qkv + (size_t)bt * QKVW;
    const size_t dst = ((size_t)(b * HH + h) * TT + t) * HD + d;

    float q1 = base[h * HD + d], q2 = base[h * HD + d + HD2];
    float qr1 = (q1 * c - q2 * s) * 0.125f;
    float qr2 = (q1 * s + q2 * c) * 0.125f;
    split1(qr1, qh[dst], ql[dst]);
    split1(qr2, qh[dst + HD2], ql[dst + HD2]);

    float k1 = base[CC + h * HD + d], k2 = base[CC + h * HD + d + HD2];
    float kr1 = k1 * c - k2 * s;
    float kr2 = k1 * s + k2 * c;
    split1(kr1, kh[dst], kl[dst]);
    split1(kr2, kh[dst + HD2], kl[dst + HD2]);

    v16[dst]       = __float2half_rn(base[2 * CC + h * HD + d]);
    v16[dst + HD2] = __float2half_rn(base[2 * CC + h * HD + d + HD2]);
}

// ---------------------------------------------------------------------------
// Flash attention: S = split-bf16 3-term; P·V = single-pass fp16.
// cp.async double-buffered K/V tiles. Br=64 (4 warps), Bc=64.
// Smem/stage: Kh 9216 + Kl 9216 + V 9216 = 27648; 2 stages = 55296.
// ---------------------------------------------------------------------------
#define KSTR2 144
#define ATT_KH 0
#define ATT_KL 9216
#define ATT_V  18432
#define ATT_STAGE 27648
#define ATT_SMEM  (2*ATT_STAGE)

__device__ __forceinline__ void att_fill(
    unsigned sb, const uint4* khp, const uint4* klp, const uint4* vp,
    int j0, int tid)
{
    const int base = j0 * 8;
    #pragma unroll
    for (int it = 0; it < 4; ++it) {
        int idx = it * 128 + tid;          // 0..511
        int r = idx >> 3, c16 = (idx & 7) * 16;
        unsigned doff = (unsigned)(r * KSTR2 + c16);
        cp16(sb + ATT_KH + doff, khp + base + idx);
        cp16(sb + ATT_KL + doff, klp + base + idx);
        cp16(sb + ATT_V  + doff, vp  + base + idx);
    }
}

__global__ __launch_bounds__(128) void attn_mma(
    const __nv_bfloat16* __restrict__ qh_g, const __nv_bfloat16* __restrict__ ql_g,
    const __nv_bfloat16* __restrict__ kh_g, const __nv_bfloat16* __restrict__ kl_g,
    const __half* __restrict__ v16_g, __half* __restrict__ o16_g)
{
    extern __shared__ __align__(16) char asm_raw[];
    const unsigned sb0 = (unsigned)__cvta_generic_to_shared(asm_raw);

    const int iTile = gridDim.x - 1 - blockIdx.x;   // heavy tiles first
    const int bh    = blockIdx.y;
    const int b = bh / HH, h = bh % HH;
    const int tid  = threadIdx.x;
    const int lane = tid & 31;
    const int wid  = tid >> 5;
    const int wr   = wid * 16;
    const int i0   = iTile * 64;
    const int g    = lane >> 2;
    const int tq   = lane & 3;

    const size_t hoff = (size_t)bh * TT * HD;

    // ---- stage Q (hi/lo) through stage-0 Kh/Kl, ldmatrix to registers ----
    {
        const uint4* qhp = (const uint4*)(qh_g + hoff + (size_t)i0 * HD);
        const uint4* qlp = (const uint4*)(ql_g + hoff + (size_t)i0 * HD);
        char* smc = asm_raw;
        #pragma unroll
        for (int it = 0; it < 4; ++it) {
            int idx = it * 128 + tid;
            int r = idx >> 3, c16 = (idx & 7) * 16;
            *(uint4*)(smc + ATT_KH + r * KSTR2 + c16) = qhp[idx];
            *(uint4*)(smc + ATT_KL + r * KSTR2 + c16) = qlp[idx];
        }
    }
    __syncthreads();

    unsigned qhf[4][4], qlf[4][4];
    {
        const unsigned aoffq = (unsigned)((wr + (lane & 15)) * KSTR2 + (lane >> 4) * 16);
        #pragma unroll
        for (int kc = 0; kc < 4; ++kc) {
            ldsm_x4(qhf[kc], sb0 + ATT_KH + aoffq + kc * 32);
            ldsm_x4(qlf[kc], sb0 + ATT_KL + aoffq + kc * 32);
        }
    }
    __syncthreads();   // Q frags read before stage-0 fill overwrites

    float m0 = -INFINITY, m1 = -INFINITY, l0 = 0.f, l1 = 0.f;
    float o[8][4];
    #pragma unroll
    for (int ni = 0; ni < 8; ni++)
        #pragma unroll
        for (int e = 0; e < 4; e++) o[ni][e] = 0.f;

    const uint4* khp = (const uint4*)(kh_g + hoff);
    const uint4* klp = (const uint4*)(kl_g + hoff);
    const uint4* vp  = (const uint4*)(v16_g + hoff);

    att_fill(sb0, khp, klp, vp, 0, tid);
    CP_COMMIT;

    for (int jT = 0; jT <= iTile; ++jT) {
        const int j0 = jT * 64;
        const unsigned sb = sb0 + (unsigned)(jT & 1) * ATT_STAGE;

        CP_WAIT(0);
        __syncthreads();   // tile jT ready; all warps done with tile jT-1

        if (jT < iTile) {
            att_fill(sb0 + (unsigned)((jT + 1) & 1) * ATT_STAGE, khp, klp, vp, j0 + 64, tid);
            CP_COMMIT;
        }

        // ---- S = Q K^T (split-bf16 3-term) ----
        float s[8][4];
        #pragma unroll
        for (int ni = 0; ni < 8; ni++)
            #pragma unroll
            for (int e = 0; e < 4; e++) s[ni][e] = 0.f;

        #pragma unroll
        for (int kc = 0; kc < 4; ++kc) {
            #pragma unroll
            for (int n2 = 0; n2 < 4; ++n2) {
                unsigned rh[4], rl[4];
                const unsigned ad = (unsigned)((n2 * 16 + (lane & 15)) * KSTR2
                                               + (lane >> 4) * 16 + kc * 32);
                ldsm_x4(rh, sb + ATT_KH + ad);
                ldsm_x4(rl, sb + ATT_KL + ad);
                mma_bf16(s[2 * n2],     qhf[kc], rh[0], rh[2]);
                mma_bf16(s[2 * n2],     qhf[kc], rl[0], rl[2]);
                mma_bf16(s[2 * n2],     qlf[kc], rh[0], rh[2]);
                mma_bf16(s[2 * n2 + 1], qhf[kc], rh[1], rh[3]);
                mma_bf16(s[2 * n2 + 1], qhf[kc], rl[1], rl[3]);
                mma_bf16(s[2 * n2 + 1], qlf[kc], rh[1], rh[3]);
            }
        }

        if (jT == iTile) {
            const int row0 = i0 + wr + g, row1 = row0 + 8;
            #pragma unroll
            for (int ni = 0; ni < 8; ++ni) {
                const int c0 = j0 + ni * 8 + tq * 2;
                if (c0 > row0)     s[ni][0] = -INFINITY;
                if (c0 + 1 > row0) s[ni][1] = -INFINITY;
                if (c0 > row1)     s[ni][2] = -INFINITY;
                if (c0 + 1 > row1) s[ni][3] = -INFINITY;
            }
        }

        // ---- online softmax ----
        float rm0 = -INFINITY, rm1 = -INFINITY;
        #pragma unroll
        for (int ni = 0; ni < 8; ++ni) {
            rm0 = fmaxf(rm0, fmaxf(s[ni][0], s[ni][1]));
            rm1 = fmaxf(rm1, fmaxf(s[ni][2], s[ni][3]));
        }
        rm0 = fmaxf(rm0, __shfl_xor_sync(0xffffffffu, rm0, 1));
        rm0 = fmaxf(rm0, __shfl_xor_sync(0xffffffffu, rm0, 2));
        rm1 = fmaxf(rm1, __shfl_xor_sync(0xffffffffu, rm1, 1));
        rm1 = fmaxf(rm1, __shfl_xor_sync(0xffffffffu, rm1, 2));

        const float mn0 = fmaxf(m0, rm0), mn1 = fmaxf(m1, rm1);
        const float al0 = __expf(m0 - mn0), al1 = __expf(m1 - mn1);
        m0 = mn0; m1 = mn1;

        unsigned pf[8][2];
        float sum0 = 0.f, sum1 = 0.f;
        #pragma unroll
        for (int ni = 0; ni < 8; ++ni) {
            float p0 = __expf(s[ni][0] - mn0);
            float p1 = __expf(s[ni][1] - mn0);
            float p2 = __expf(s[ni][2] - mn1);
            float p3 = __expf(s[ni][3] - mn1);
            sum0 += p0 + p1; sum1 += p2 + p3;
            __half2 h01 = __floats2half2_rn(p0, p1);
            __half2 h23 = __floats2half2_rn(p2, p3);
            pf[ni][0] = *(unsigned*)&h01;
            pf[ni][1] = *(unsigned*)&h23;
        }
        sum0 += __shfl_xor_sync(0xffffffffu, sum0, 1);
        sum0 += __shfl_xor_sync(0xffffffffu, sum0, 2);
        sum1 += __shfl_xor_sync(0xffffffffu, sum1, 1);
        sum1 += __shfl_xor_sync(0xffffffffu, sum1, 2);
        l0 = l0 * al0 + sum0;
        l1 = l1 * al1 + sum1;

        #pragma unroll
        for (int ni = 0; ni < 8; ++ni) {
            o[ni][0] *= al0; o[ni][1] *= al0;
            o[ni][2] *= al1; o[ni][3] *= al1;
        }

        // ---- O += P V (single-pass fp16) ----
        #pragma unroll
        for (int kc = 0; kc < 4; ++kc) {
            unsigned ap[4] = { pf[2 * kc][0], pf[2 * kc][1], pf[2 * kc + 1][0], pf[2 * kc + 1][1] };
            #pragma unroll
            for (int n2 = 0; n2 < 4; ++n2) {
                unsigned v4[4];
                const unsigned ad = (unsigned)(ATT_V + (kc * 16 + (lane & 15)) * KSTR2
                                               + (n2 * 2 + (lane >> 4)) * 16);
                ldsm_x4_t(v4, sb + ad);
                mma_fp16(o[2 * n2],     ap, v4[0], v4[1]);
                mma_fp16(o[2 * n2 + 1], ap, v4[2], v4[3]);
            }
        }
    }

    // ---- normalize + store fp16 ----
    const float inv0 = 1.f / l0, inv1 = 1.f / l1;
    const int row0 = i0 + wr + g;
    #pragma unroll
    for (int ni = 0; ni < 8; ++ni) {
        const int col = h * HD + ni * 8 + tq * 2;
        const size_t i0a = (size_t)(b * TT + row0) * CC + col;
        const size_t i1a = (size_t)(b * TT + row0 + 8) * CC + col;
        __half2 v0 = __floats2half2_rn(o[ni][0] * inv0, o[ni][1] * inv0);
        __half2 v1 = __floats2half2_rn(o[ni][2] * inv1, o[ni][3] * inv1);
        *(__half2*)(o16_g + i0a) = v0;
        *(__half2*)(o16_g + i1a) = v1;
    }
}

// ---------------------------------------------------------------------------
// Launch
// ---------------------------------------------------------------------------
extern "C" void kernel_launch(void* const* d_in, const int* in_sizes, int n_in,
                              void* d_out, int out_size)
{
    const float* x     = (const float*)d_in[0];
    const float* fcos  = (const float*)d_in[1];
    const float* fsin  = (const float*)d_in[2];
    const float* Wqkv  = (const float*)d_in[3];
    const float* bqkv  = (const float*)d_in[4];
    const float* Wproj = (const float*)d_in[5];
    const float* bproj = (const float*)d_in[6];
    float* out = (float*)d_out;

    float* qkv;
    __half *x16, *o16, *wq16, *wp16, *v16;
    __nv_bfloat16 *qh, *ql, *kh, *kl;
    cudaGetSymbolAddress((void**)&qkv, g_qkv);
    cudaGetSymbolAddress((void**)&x16, g_x16);
    cudaGetSymbolAddress((void**)&o16, g_o16);
    cudaGetSymbolAddress((void**)&wq16, g_wq16);
    cudaGetSymbolAddress((void**)&wp16, g_wp16);
    cudaGetSymbolAddress((void**)&qh, g_qh);   cudaGetSymbolAddress((void**)&ql, g_ql);
    cudaGetSymbolAddress((void**)&kh, g_kh);   cudaGetSymbolAddress((void**)&kl, g_kl);
    cudaGetSymbolAddress((void**)&v16, g_v16);

    cudaFuncSetAttribute(hgemm, cudaFuncAttributeMaxDynamicSharedMemorySize, GSMEM);
    cudaFuncSetAttribute(attn_mma, cudaFuncAttributeMaxDynamicSharedMemorySize, ATT_SMEM);

    // 0) prep
    convhalf<<<(MROWS * CC) / 1024, 256>>>(x, x16);
    {
        dim3 g1(QKVW / 32, CC / 32);
        transpose_half<<<g1, 256>>>(Wqkv, wq16, CC, QKVW);
        dim3 g2(CC / 32, CC / 32);
        transpose_half<<<g2, 256>>>(Wproj, wp16, CC, CC);
    }

    // 1) QKV = x @ Wqkv + bqkv
    {
        dim3 grid(QKVW / 128, MROWS / 128);   // (24, 32)
        hgemm<<<grid, 256, GSMEM>>>(x16, wq16, bqkv, qkv, MROWS, QKVW, CC);
    }
    // 2) RoPE + split
    rope_split<<<MROWS, 512>>>(qkv, fcos, fsin, qh, ql, kh, kl, v16);

    // 3) Flash attention -> fp16 att
    {
        dim3 grid(TT / 64, BB * HH);
        attn_mma<<<grid, 128, ATT_SMEM>>>(qh, ql, kh, kl, v16, o16);
    }
    // 4) out = att @ Wproj + bproj
    {
        dim3 grid(CC / 128, MROWS / 128);     // (8, 32)
        hgemm<<<grid, 256, GSMEM>>>(o16, wp16, bproj, out, MROWS, CC, CC);
    }
}

// round 8
// speedup vs baseline: 1.8386x; 1.0116x over previous
#include <cuda_runtime.h>
#include <cuda_bf16.h>
#include <cuda_fp16.h>
#include <math.h>
#include <stdint.h>

// Problem constants
#define BB   2
#define TT   2048
#define CC   1024
#define HH   16
#define HD   64
#define HD2  32
#define MROWS (BB*TT)          // 4096
#define QKVW (3*CC)            // 3072

// Scratch (allocation-free rule: __device__ globals)
__device__ __half g_x16[(size_t)MROWS * CC];                // x fp16 [M][K]
__device__ __half g_o16[(size_t)MROWS * CC];                // attention out fp16 [M][K]
__device__ __half g_wq16[(size_t)QKVW * CC];                // Wqkv^T fp16 [N][K]
__device__ __half g_wp16[(size_t)CC * CC];                  // Wproj^T fp16 [N][K]
// Head-contiguous q/k bf16 hi/lo + v fp16: [b*H+h][T][64]
#define HELEMS ((size_t)BB * HH * TT * HD)
__device__ __nv_bfloat16 g_qh[HELEMS], g_ql[HELEMS];
__device__ __nv_bfloat16 g_kh[HELEMS], g_kl[HELEMS];
__device__ __half        g_v16[HELEMS];

// ---------------------------------------------------------------------------
// Helpers
// ---------------------------------------------------------------------------
__device__ __forceinline__ void split1(float x, __nv_bfloat16 &h, __nv_bfloat16 &l)
{
    h = __float2bfloat16(x);
    l = __float2bfloat16(x - __bfloat162float(h));
}

__device__ __forceinline__ void ldsm_x4(unsigned r[4], unsigned addr)
{
    asm volatile("ldmatrix.sync.aligned.m8n8.x4.shared.b16 {%0,%1,%2,%3}, [%4];"
                 : "=r"(r[0]), "=r"(r[1]), "=r"(r[2]), "=r"(r[3]) : "r"(addr));
}

__device__ __forceinline__ void ldsm_x4_t(unsigned r[4], unsigned addr)
{
    asm volatile("ldmatrix.sync.aligned.m8n8.x4.trans.shared.b16 {%0,%1,%2,%3}, [%4];"
                 : "=r"(r[0]), "=r"(r[1]), "=r"(r[2]), "=r"(r[3]) : "r"(addr));
}

__device__ __forceinline__ void mma_bf16(float d[4], const unsigned a[4], unsigned b0, unsigned b1)
{
    asm volatile("mma.sync.aligned.m16n8k16.row.col.f32.bf16.bf16.f32 "
                 "{%0,%1,%2,%3}, {%4,%5,%6,%7}, {%8,%9}, {%0,%1,%2,%3};"
                 : "+f"(d[0]), "+f"(d[1]), "+f"(d[2]), "+f"(d[3])
                 : "r"(a[0]), "r"(a[1]), "r"(a[2]), "r"(a[3]), "r"(b0), "r"(b1));
}

__device__ __forceinline__ void mma_fp16(float d[4], const unsigned a[4], unsigned b0, unsigned b1)
{
    asm volatile("mma.sync.aligned.m16n8k16.row.col.f32.f16.f16.f32 "
                 "{%0,%1,%2,%3}, {%4,%5,%6,%7}, {%8,%9}, {%0,%1,%2,%3};"
                 : "+f"(d[0]), "+f"(d[1]), "+f"(d[2]), "+f"(d[3])
                 : "r"(a[0]), "r"(a[1]), "r"(a[2]), "r"(a[3]), "r"(b0), "r"(b1));
}

__device__ __forceinline__ void cp16(unsigned dst, const void* src)
{
    asm volatile("cp.async.cg.shared.global [%0], [%1], 16;" :: "r"(dst), "l"(src));
}
#define CP_COMMIT  asm volatile("cp.async.commit_group;" ::: "memory")
#define CP_WAIT(n) asm volatile("cp.async.wait_group %0;" :: "n"(n) : "memory")

// ---------------------------------------------------------------------------
// Prep kernels
// ---------------------------------------------------------------------------
__global__ __launch_bounds__(256) void convhalf(
    const float* __restrict__ X, __half* __restrict__ X16)
{
    int i = (blockIdx.x * 256 + threadIdx.x) * 4;
    float4 v = *(const float4*)(X + i);
    __half2 a = __floats2half2_rn(v.x, v.y);
    __half2 b = __floats2half2_rn(v.z, v.w);
    *(uint2*)(X16 + i) = make_uint2(*(unsigned*)&a, *(unsigned*)&b);
}

__global__ __launch_bounds__(256) void transpose_half(
    const float* __restrict__ W, __half* __restrict__ Wt, int K, int N)
{
    __shared__ float tile[32][33];
    const int n0 = blockIdx.x * 32, k0 = blockIdx.y * 32;
    const int tx = threadIdx.x & 31, ty = threadIdx.x >> 5;
    #pragma unroll
    for (int i = 0; i < 32; i += 8)
        tile[ty + i][tx] = W[(size_t)(k0 + ty + i) * N + n0 + tx];
    __syncthreads();
    #pragma unroll
    for (int i = 0; i < 32; i += 8)
        Wt[(size_t)(n0 + ty + i) * K + k0 + tx] = __float2half_rn(tile[tx][ty + i]);
}

// ---------------------------------------------------------------------------
// Shared GEMM mainloop config: CTA 128x128, BK=32, 256 threads (8 warps 2x4,
// warp tile 64x32). fp16 single-pass, 4-stage cp.async ring.
// ---------------------------------------------------------------------------
#define GROW   80
#define GMAT   (128*GROW)             // 10240
#define GSTAGE (2*GMAT)               // 20480
#define GSMEM  (4*GSTAGE)             // 81920
#define EPSTR  132                    // epilogue staging stride (floats)

__device__ __forceinline__ void h_fill(
    unsigned sb,
    const __half* __restrict__ A_g, const __half* __restrict__ B_g,
    int row0, int col0, int K, int kbase, int tid)
{
    #pragma unroll
    for (int it = 0; it < 2; ++it) {
        int idx = it * 256 + tid;
        int r = idx >> 2;
        int c = idx & 3;
        unsigned doff = (unsigned)(r * GROW + c * 16);
        cp16(sb + doff,        A_g + (size_t)(row0 + r) * K + kbase + c * 8);
        cp16(sb + GMAT + doff, B_g + (size_t)(col0 + r) * K + kbase + c * 8);
    }
}

// Mainloop producing acc[4][4][4] for this thread's warp tile.
__device__ __forceinline__ void h_mainloop(
    unsigned sb0, const __half* A_g, const __half* B_g,
    int row0, int col0, int K, int tid, float acc[4][4][4])
{
    const int lane = tid & 31;
    const int wid  = tid >> 5;
    const int wm   = wid >> 2;
    const int wn   = wid & 3;

    #pragma unroll
    for (int mi = 0; mi < 4; mi++)
        #pragma unroll
        for (int ni = 0; ni < 4; ni++)
            #pragma unroll
            for (int e = 0; e < 4; e++) acc[mi][ni][e] = 0.f;

    const int KT = K >> 5;

    h_fill(sb0,              A_g, B_g, row0, col0, K, 0,  tid); CP_COMMIT;
    h_fill(sb0 + GSTAGE,     A_g, B_g, row0, col0, K, 32, tid); CP_COMMIT;
    h_fill(sb0 + 2 * GSTAGE, A_g, B_g, row0, col0, K, 64, tid); CP_COMMIT;

    const unsigned aoff = (unsigned)((wm * 64 + (lane & 15)) * GROW + (lane >> 4) * 16);
    const unsigned boff = (unsigned)(GMAT + (wn * 32 + (lane & 15)) * GROW + (lane >> 4) * 16);

    for (int kt = 0; kt < KT; ++kt) {
        const unsigned sb = sb0 + (unsigned)(kt & 3) * GSTAGE;

        const int rem = KT - 1 - kt;
        if (rem >= 2)      CP_WAIT(2);
        else if (rem == 1) CP_WAIT(1);
        else               CP_WAIT(0);
        __syncthreads();

        if (kt + 3 < KT) {
            h_fill(sb0 + (unsigned)((kt + 3) & 3) * GSTAGE,
                   A_g, B_g, row0, col0, K, (kt + 3) * 32, tid);
            CP_COMMIT;
        }

        #pragma unroll
        for (int kc = 0; kc < 2; ++kc) {
            unsigned af[4][4], bf[2][4];
            #pragma unroll
            for (int n2 = 0; n2 < 2; ++n2)
                ldsm_x4(bf[n2], sb + boff + n2 * 16 * GROW + kc * 32);
            #pragma unroll
            for (int mi = 0; mi < 4; ++mi)
                ldsm_x4(af[mi], sb + aoff + mi * 16 * GROW + kc * 32);
            #pragma unroll
            for (int mi = 0; mi < 4; ++mi)
                #pragma unroll
                for (int n2 = 0; n2 < 2; ++n2) {
                    mma_fp16(acc[mi][2 * n2],     af[mi], bf[n2][0], bf[n2][2]);
                    mma_fp16(acc[mi][2 * n2 + 1], af[mi], bf[n2][1], bf[n2][3]);
                }
        }
    }
}

// ---------------------------------------------------------------------------
// Proj GEMM: fp32 output + bias.
// ---------------------------------------------------------------------------
__global__ __launch_bounds__(256) void hgemm(
    const __half* __restrict__ A_g, const __half* __restrict__ B_g,
    const float* __restrict__ bias, float* __restrict__ Cm,
    int M, int N, int K)
{
    extern __shared__ __align__(16) char smem[];
    const unsigned sb0 = (unsigned)__cvta_generic_to_shared(smem);
    const int tid  = threadIdx.x;
    const int lane = tid & 31;
    const int wid  = tid >> 5;
    const int wm   = wid >> 2;
    const int wn   = wid & 3;
    const int row0 = blockIdx.y * 128;
    const int col0 = blockIdx.x * 128;

    float acc[4][4][4];
    h_mainloop(sb0, A_g, B_g, row0, col0, K, tid, acc);

    const int g  = lane >> 2;
    const int tq = lane & 3;
    #pragma unroll
    for (int mi = 0; mi < 4; mi++) {
        const int r0 = row0 + wm * 64 + mi * 16 + g;
        #pragma unroll
        for (int ni = 0; ni < 4; ni++) {
            const int c = col0 + wn * 32 + (ni >> 1) * 16 + (ni & 1) * 8 + tq * 2;
            const float bz0 = bias[c], bz1 = bias[c + 1];
            *(float2*)(Cm + (size_t)r0 * N + c) =
                make_float2(acc[mi][ni][0] + bz0, acc[mi][ni][1] + bz1);
            *(float2*)(Cm + (size_t)(r0 + 8) * N + c) =
                make_float2(acc[mi][ni][2] + bz0, acc[mi][ni][3] + bz1);
        }
    }
}

// ---------------------------------------------------------------------------
// QKV GEMM with fused bias + RoPE + split epilogue.
// Output tile (128 cols) lies wholly in q, k or v region; RoPE pairs
// (d, d+32) are within a 64-wide head, hence within the tile.
// ---------------------------------------------------------------------------
__global__ __launch_bounds__(256) void hgemm_qkv(
    const __half* __restrict__ A_g, const __half* __restrict__ B_g,
    const float* __restrict__ bias,
    const float* __restrict__ cosf_, const float* __restrict__ sinf_,
    __nv_bfloat16* __restrict__ qh, __nv_bfloat16* __restrict__ ql,
    __nv_bfloat16* __restrict__ kh, __nv_bfloat16* __restrict__ kl,
    __half* __restrict__ v16, int K)
{
    extern __shared__ __align__(16) char smem[];
    const unsigned sb0 = (unsigned)__cvta_generic_to_shared(smem);
    const int tid  = threadIdx.x;
    const int lane = tid & 31;
    const int wid  = tid >> 5;
    const int wm   = wid >> 2;
    const int wn   = wid & 3;
    const int row0 = blockIdx.y * 128;
    const int col0 = blockIdx.x * 128;

    float acc[4][4][4];
    h_mainloop(sb0, A_g, B_g, row0, col0, K, tid, acc);

    // stage fp32 tile (+bias) into smem
    __syncthreads();          // all warps past final mainloop reads
    float* sepi = (float*)smem;
    {
        const int g  = lane >> 2;
        const int tq = lane & 3;
        #pragma unroll
        for (int mi = 0; mi < 4; mi++) {
            const int r = wm * 64 + mi * 16 + g;
            #pragma unroll
            for (int ni = 0; ni < 4; ni++) {
                const int c = wn * 32 + (ni >> 1) * 16 + (ni & 1) * 8 + tq * 2;
                const float bz0 = bias[col0 + c], bz1 = bias[col0 + c + 1];
                sepi[r * EPSTR + c]           = acc[mi][ni][0] + bz0;
                sepi[r * EPSTR + c + 1]       = acc[mi][ni][1] + bz1;
                sepi[(r + 8) * EPSTR + c]     = acc[mi][ni][2] + bz0;
                sepi[(r + 8) * EPSTR + c + 1] = acc[mi][ni][3] + bz1;
            }
        }
    }
    __syncthreads();

    if (col0 < 2 * CC) {
        // q or k region: RoPE + bf16 hi/lo split
        const bool isQ = (col0 < CC);
        const int hbase = (col0 & (CC - 1)) >> 6;   // first head in tile
        #pragma unroll
        for (int it = 0; it < 32; ++it) {
            int idx = it * 256 + tid;      // 0..8191
            int r   = idx >> 6;            // 0..127
            int pc  = idx & 63;
            int head = pc >> 5, d = pc & 31;
            int c1 = head * 64 + d;
            int row = row0 + r;
            int b = row >> 11, t = row & (TT - 1);

            float v1 = sepi[r * EPSTR + c1];
            float v2 = sepi[r * EPSTR + c1 + 32];
            float ct = cosf_[t * HD2 + d];
            float st = sinf_[t * HD2 + d];
            float r1 = v1 * ct - v2 * st;
            float r2 = v1 * st + v2 * ct;

            size_t dst = ((size_t)(b * HH + hbase + head) * TT + t) * HD + d;
            if (isQ) {
                r1 *= 0.125f; r2 *= 0.125f;
                split1(r1, qh[dst], ql[dst]);
                split1(r2, qh[dst + HD2], ql[dst + HD2]);
            } else {
                split1(r1, kh[dst], kl[dst]);
                split1(r2, kh[dst + HD2], kl[dst + HD2]);
            }
        }
    } else {
        // v region: fp16 convert
        const int hbase = (col0 - 2 * CC) >> 6;
        #pragma unroll
        for (int it = 0; it < 32; ++it) {
            int idx = it * 256 + tid;      // 0..8191
            int r   = idx >> 6;            // 0..127
            int c   = (idx & 63) * 2;      // 0..126
            int head = c >> 6, d = c & 63;
            int row = row0 + r;
            int b = row >> 11, t = row & (TT - 1);
            float v1 = sepi[r * EPSTR + c];
            float v2 = sepi[r * EPSTR + c + 1];
            size_t dst = ((size_t)(b * HH + hbase + head) * TT + t) * HD + d;
            *(__half2*)(v16 + dst) = __floats2half2_rn(v1, v2);
        }
    }
}

// ---------------------------------------------------------------------------
// Flash attention: S = split-bf16 3-term; P·V = single-pass fp16.
// cp.async double-buffered K/V tiles. Br=64 (4 warps), Bc=64.
// ---------------------------------------------------------------------------
#define KSTR2 144
#define ATT_KH 0
#define ATT_KL 9216
#define ATT_V  18432
#define ATT_STAGE 27648
#define ATT_SMEM  (2*ATT_STAGE)

__device__ __forceinline__ void att_fill(
    unsigned sb, const uint4* khp, const uint4* klp, const uint4* vp,
    int j0, int tid)
{
    const int base = j0 * 8;
    #pragma unroll
    for (int it = 0; it < 4; ++it) {
        int idx = it * 128 + tid;
        int r = idx >> 3, c16 = (idx & 7) * 16;
        unsigned doff = (unsigned)(r * KSTR2 + c16);
        cp16(sb + ATT_KH + doff, khp + base + idx);
        cp16(sb + ATT_KL + doff, klp + base + idx);
        cp16(sb + ATT_V  + doff, vp  + base + idx);
    }
}

__global__ __launch_bounds__(128) void attn_mma(
    const __nv_bfloat16* __restrict__ qh_g, const __nv_bfloat16* __restrict__ ql_g,
    const __nv_bfloat16* __restrict__ kh_g, const __nv_bfloat16* __restrict__ kl_g,
    const __half* __restrict__ v16_g, __half* __restrict__ o16_g)
{
    extern __shared__ __align__(16) char asm_raw[];
    const unsigned sb0 = (unsigned)__cvta_generic_to_shared(asm_raw);

    const int iTile = gridDim.x - 1 - blockIdx.x;
    const int bh    = blockIdx.y;
    const int b = bh / HH, h = bh % HH;
    const int tid  = threadIdx.x;
    const int lane = tid & 31;
    const int wid  = tid >> 5;
    const int wr   = wid * 16;
    const int i0   = iTile * 64;
    const int g    = lane >> 2;
    const int tq   = lane & 3;

    const size_t hoff = (size_t)bh * TT * HD;

    {
        const uint4* qhp = (const uint4*)(qh_g + hoff + (size_t)i0 * HD);
        const uint4* qlp = (const uint4*)(ql_g + hoff + (size_t)i0 * HD);
        char* smc = asm_raw;
        #pragma unroll
        for (int it = 0; it < 4; ++it) {
            int idx = it * 128 + tid;
            int r = idx >> 3, c16 = (idx & 7) * 16;
            *(uint4*)(smc + ATT_KH + r * KSTR2 + c16) = qhp[idx];
            *(uint4*)(smc + ATT_KL + r * KSTR2 + c16) = qlp[idx];
        }
    }
    __syncthreads();

    unsigned qhf[4][4], qlf[4][4];
    {
        const unsigned aoffq = (unsigned)((wr + (lane & 15)) * KSTR2 + (lane >> 4) * 16);
        #pragma unroll
        for (int kc = 0; kc < 4; ++kc) {
            ldsm_x4(qhf[kc], sb0 + ATT_KH + aoffq + kc * 32);
            ldsm_x4(qlf[kc], sb0 + ATT_KL + aoffq + kc * 32);
        }
    }
    __syncthreads();

    float m0 = -INFINITY, m1 = -INFINITY, l0 = 0.f, l1 = 0.f;
    float o[8][4];
    #pragma unroll
    for (int ni = 0; ni < 8; ni++)
        #pragma unroll
        for (int e = 0; e < 4; e++) o[ni][e] = 0.f;

    const uint4* khp = (const uint4*)(kh_g + hoff);
    const uint4* klp = (const uint4*)(kl_g + hoff);
    const uint4* vp  = (const uint4*)(v16_g + hoff);

    att_fill(sb0, khp, klp, vp, 0, tid);
    CP_COMMIT;

    for (int jT = 0; jT <= iTile; ++jT) {
        const int j0 = jT * 64;
        const unsigned sb = sb0 + (unsigned)(jT & 1) * ATT_STAGE;

        CP_WAIT(0);
        __syncthreads();

        if (jT < iTile) {
            att_fill(sb0 + (unsigned)((jT + 1) & 1) * ATT_STAGE, khp, klp, vp, j0 + 64, tid);
            CP_COMMIT;
        }

        float s[8][4];
        #pragma unroll
        for (int ni = 0; ni < 8; ni++)
            #pragma unroll
            for (int e = 0; e < 4; e++) s[ni][e] = 0.f;

        #pragma unroll
        for (int kc = 0; kc < 4; ++kc) {
            #pragma unroll
            for (int n2 = 0; n2 < 4; ++n2) {
                unsigned rh[4], rl[4];
                const unsigned ad = (unsigned)((n2 * 16 + (lane & 15)) * KSTR2
                                               + (lane >> 4) * 16 + kc * 32);
                ldsm_x4(rh, sb + ATT_KH + ad);
                ldsm_x4(rl, sb + ATT_KL + ad);
                mma_bf16(s[2 * n2],     qhf[kc], rh[0], rh[2]);
                mma_bf16(s[2 * n2],     qhf[kc], rl[0], rl[2]);
                mma_bf16(s[2 * n2],     qlf[kc], rh[0], rh[2]);
                mma_bf16(s[2 * n2 + 1], qhf[kc], rh[1], rh[3]);
                mma_bf16(s[2 * n2 + 1], qhf[kc], rl[1], rl[3]);
                mma_bf16(s[2 * n2 + 1], qlf[kc], rh[1], rh[3]);
            }
        }

        if (jT == iTile) {
            const int row0 = i0 + wr + g, row1 = row0 + 8;
            #pragma unroll
            for (int ni = 0; ni < 8; ++ni) {
                const int c0 = j0 + ni * 8 + tq * 2;
                if (c0 > row0)     s[ni][0] = -INFINITY;
                if (c0 + 1 > row0) s[ni][1] = -INFINITY;
                if (c0 > row1)     s[ni][2] = -INFINITY;
                if (c0 + 1 > row1) s[ni][3] = -INFINITY;
            }
        }

        float rm0 = -INFINITY, rm1 = -INFINITY;
        #pragma unroll
        for (int ni = 0; ni < 8; ++ni) {
            rm0 = fmaxf(rm0, fmaxf(s[ni][0], s[ni][1]));
            rm1 = fmaxf(rm1, fmaxf(s[ni][2], s[ni][3]));
        }
        rm0 = fmaxf(rm0, __shfl_xor_sync(0xffffffffu, rm0, 1));
        rm0 = fmaxf(rm0, __shfl_xor_sync(0xffffffffu, rm0, 2));
        rm1 = fmaxf(rm1, __shfl_xor_sync(0xffffffffu, rm1, 1));
        rm1 = fmaxf(rm1, __shfl_xor_sync(0xffffffffu, rm1, 2));

        const float mn0 = fmaxf(m0, rm0), mn1 = fmaxf(m1, rm1);
        const float al0 = __expf(m0 - mn0), al1 = __expf(m1 - mn1);
        m0 = mn0; m1 = mn1;

        unsigned pf[8][2];
        float sum0 = 0.f, sum1 = 0.f;
        #pragma unroll
        for (int ni = 0; ni < 8; ++ni) {
            float p0 = __expf(s[ni][0] - mn0);
            float p1 = __expf(s[ni][1] - mn0);
            float p2 = __expf(s[ni][2] - mn1);
            float p3 = __expf(s[ni][3] - mn1);
            sum0 += p0 + p1; sum1 += p2 + p3;
            __half2 h01 = __floats2half2_rn(p0, p1);
            __half2 h23 = __floats2half2_rn(p2, p3);
            pf[ni][0] = *(unsigned*)&h01;
            pf[ni][1] = *(unsigned*)&h23;
        }
        sum0 += __shfl_xor_sync(0xffffffffu, sum0, 1);
        sum0 += __shfl_xor_sync(0xffffffffu, sum0, 2);
        sum1 += __shfl_xor_sync(0xffffffffu, sum1, 1);
        sum1 += __shfl_xor_sync(0xffffffffu, sum1, 2);
        l0 = l0 * al0 + sum0;
        l1 = l1 * al1 + sum1;

        #pragma unroll
        for (int ni = 0; ni < 8; ++ni) {
            o[ni][0] *= al0; o[ni][1] *= al0;
            o[ni][2] *= al1; o[ni][3] *= al1;
        }

        #pragma unroll
        for (int kc = 0; kc < 4; ++kc) {
            unsigned ap[4] = { pf[2 * kc][0], pf[2 * kc][1], pf[2 * kc + 1][0], pf[2 * kc + 1][1] };
            #pragma unroll
            for (int n2 = 0; n2 < 4; ++n2) {
                unsigned v4[4];
                const unsigned ad = (unsigned)(ATT_V + (kc * 16 + (lane & 15)) * KSTR2
                                               + (n2 * 2 + (lane >> 4)) * 16);
                ldsm_x4_t(v4, sb + ad);
                mma_fp16(o[2 * n2],     ap, v4[0], v4[1]);
                mma_fp16(o[2 * n2 + 1], ap, v4[2], v4[3]);
            }
        }
    }

    const float inv0 = 1.f / l0, inv1 = 1.f / l1;
    const int row0 = i0 + wr + g;
    #pragma unroll
    for (int ni = 0; ni < 8; ++ni) {
        const int col = h * HD + ni * 8 + tq * 2;
        const size_t i0a = (size_t)(b * TT + row0) * CC + col;
        const size_t i1a = (size_t)(b * TT + row0 + 8) * CC + col;
        __half2 v0 = __floats2half2_rn(o[ni][0] * inv0, o[ni][1] * inv0);
        __half2 v1 = __floats2half2_rn(o[ni][2] * inv1, o[ni][3] * inv1);
        *(__half2*)(o16_g + i0a) = v0;
        *(__half2*)(o16_g + i1a) = v1;
    }
}

// ---------------------------------------------------------------------------
// Launch
// ---------------------------------------------------------------------------
extern "C" void kernel_launch(void* const* d_in, const int* in_sizes, int n_in,
                              void* d_out, int out_size)
{
    const float* x     = (const float*)d_in[0];
    const float* fcos  = (const float*)d_in[1];
    const float* fsin  = (const float*)d_in[2];
    const float* Wqkv  = (const float*)d_in[3];
    const float* bqkv  = (const float*)d_in[4];
    const float* Wproj = (const float*)d_in[5];
    const float* bproj = (const float*)d_in[6];
    float* out = (float*)d_out;

    __half *x16, *o16, *wq16, *wp16, *v16;
    __nv_bfloat16 *qh, *ql, *kh, *kl;
    cudaGetSymbolAddress((void**)&x16, g_x16);
    cudaGetSymbolAddress((void**)&o16, g_o16);
    cudaGetSymbolAddress((void**)&wq16, g_wq16);
    cudaGetSymbolAddress((void**)&wp16, g_wp16);
    cudaGetSymbolAddress((void**)&qh, g_qh);   cudaGetSymbolAddress((void**)&ql, g_ql);
    cudaGetSymbolAddress((void**)&kh, g_kh);   cudaGetSymbolAddress((void**)&kl, g_kl);
    cudaGetSymbolAddress((void**)&v16, g_v16);

    cudaFuncSetAttribute(hgemm, cudaFuncAttributeMaxDynamicSharedMemorySize, GSMEM);
    cudaFuncSetAttribute(hgemm_qkv, cudaFuncAttributeMaxDynamicSharedMemorySize, GSMEM);
    cudaFuncSetAttribute(attn_mma, cudaFuncAttributeMaxDynamicSharedMemorySize, ATT_SMEM);

    // 0) prep
    convhalf<<<(MROWS * CC) / 1024, 256>>>(x, x16);
    {
        dim3 g1(QKVW / 32, CC / 32);
        transpose_half<<<g1, 256>>>(Wqkv, wq16, CC, QKVW);
        dim3 g2(CC / 32, CC / 32);
        transpose_half<<<g2, 256>>>(Wproj, wp16, CC, CC);
    }

    // 1) QKV GEMM with fused bias+RoPE+split epilogue
    {
        dim3 grid(QKVW / 128, MROWS / 128);   // (24, 32)
        hgemm_qkv<<<grid, 256, GSMEM>>>(x16, wq16, bqkv, fcos, fsin,
                                        qh, ql, kh, kl, v16, CC);
    }
    // 2) Flash attention -> fp16 att
    {
        dim3 grid(TT / 64, BB * HH);
        attn_mma<<<grid, 128, ATT_SMEM>>>(qh, ql, kh, kl, v16, o16);
    }
    // 3) out = att @ Wproj + bproj
    {
        dim3 grid(CC / 128, MROWS / 128);     // (8, 32)
        hgemm<<<grid, 256, GSMEM>>>(o16, wp16, bproj, out, MROWS, CC, CC);
    }
}

// round 9
// speedup vs baseline: 2.2746x; 1.2371x over previous
#include <cuda_runtime.h>
#include <cuda_bf16.h>
#include <cuda_fp16.h>
#include <math.h>
#include <stdint.h>

// Problem constants
#define BB   2
#define TT   2048
#define CC   1024
#define HH   16
#define HD   64
#define HD2  32
#define MROWS (BB*TT)          // 4096
#define QKVW (3*CC)            // 3072

// Scratch (allocation-free rule: __device__ globals)
__device__ __half g_x16[(size_t)MROWS * CC];                // x fp16 [M][K]
__device__ __half g_o16[(size_t)MROWS * CC];                // attention out fp16 [M][K]
__device__ __half g_wq16[(size_t)QKVW * CC];                // Wqkv^T fp16 [N][K]
__device__ __half g_wp16[(size_t)CC * CC];                  // Wproj^T fp16 [N][K]
// Head-contiguous fp16 q (pre-scaled 1/8), k, v: [b*H+h][T][64]
#define HELEMS ((size_t)BB * HH * TT * HD)
__device__ __half g_q16[HELEMS], g_k16[HELEMS], g_v16[HELEMS];

// ---------------------------------------------------------------------------
// Helpers
// ---------------------------------------------------------------------------
__device__ __forceinline__ void ldsm_x4(unsigned r[4], unsigned addr)
{
    asm volatile("ldmatrix.sync.aligned.m8n8.x4.shared.b16 {%0,%1,%2,%3}, [%4];"
                 : "=r"(r[0]), "=r"(r[1]), "=r"(r[2]), "=r"(r[3]) : "r"(addr));
}

__device__ __forceinline__ void ldsm_x4_t(unsigned r[4], unsigned addr)
{
    asm volatile("ldmatrix.sync.aligned.m8n8.x4.trans.shared.b16 {%0,%1,%2,%3}, [%4];"
                 : "=r"(r[0]), "=r"(r[1]), "=r"(r[2]), "=r"(r[3]) : "r"(addr));
}

__device__ __forceinline__ void mma_fp16(float d[4], const unsigned a[4], unsigned b0, unsigned b1)
{
    asm volatile("mma.sync.aligned.m16n8k16.row.col.f32.f16.f16.f32 "
                 "{%0,%1,%2,%3}, {%4,%5,%6,%7}, {%8,%9}, {%0,%1,%2,%3};"
                 : "+f"(d[0]), "+f"(d[1]), "+f"(d[2]), "+f"(d[3])
                 : "r"(a[0]), "r"(a[1]), "r"(a[2]), "r"(a[3]), "r"(b0), "r"(b1));
}

__device__ __forceinline__ void cp16(unsigned dst, const void* src)
{
    asm volatile("cp.async.cg.shared.global [%0], [%1], 16;" :: "r"(dst), "l"(src));
}
#define CP_COMMIT  asm volatile("cp.async.commit_group;" ::: "memory")
#define CP_WAIT(n) asm volatile("cp.async.wait_group %0;" :: "n"(n) : "memory")

// ---------------------------------------------------------------------------
// Prep kernels
// ---------------------------------------------------------------------------
__global__ __launch_bounds__(256) void convhalf(
    const float* __restrict__ X, __half* __restrict__ X16)
{
    int i = (blockIdx.x * 256 + threadIdx.x) * 4;
    float4 v = *(const float4*)(X + i);
    __half2 a = __floats2half2_rn(v.x, v.y);
    __half2 b = __floats2half2_rn(v.z, v.w);
    *(uint2*)(X16 + i) = make_uint2(*(unsigned*)&a, *(unsigned*)&b);
}

__global__ __launch_bounds__(256) void transpose_half(
    const float* __restrict__ W, __half* __restrict__ Wt, int K, int N)
{
    __shared__ float tile[32][33];
    const int n0 = blockIdx.x * 32, k0 = blockIdx.y * 32;
    const int tx = threadIdx.x & 31, ty = threadIdx.x >> 5;
    #pragma unroll
    for (int i = 0; i < 32; i += 8)
        tile[ty + i][tx] = W[(size_t)(k0 + ty + i) * N + n0 + tx];
    __syncthreads();
    #pragma unroll
    for (int i = 0; i < 32; i += 8)
        Wt[(size_t)(n0 + ty + i) * K + k0 + tx] = __float2half_rn(tile[tx][ty + i]);
}

// ---------------------------------------------------------------------------
// Shared GEMM mainloop: CTA 128x128, BK=32, 256 threads (8 warps 2x4,
// warp tile 64x32). fp16 single-pass, 4-stage cp.async ring.
// ---------------------------------------------------------------------------
#define GROW   80
#define GMAT   (128*GROW)             // 10240
#define GSTAGE (2*GMAT)               // 20480
#define GSMEM  (4*GSTAGE)             // 81920
#define EPSTR  132                    // epilogue staging stride (floats)

__device__ __forceinline__ void h_fill(
    unsigned sb,
    const __half* __restrict__ A_g, const __half* __restrict__ B_g,
    int row0, int col0, int K, int kbase, int tid)
{
    #pragma unroll
    for (int it = 0; it < 2; ++it) {
        int idx = it * 256 + tid;
        int r = idx >> 2;
        int c = idx & 3;
        unsigned doff = (unsigned)(r * GROW + c * 16);
        cp16(sb + doff,        A_g + (size_t)(row0 + r) * K + kbase + c * 8);
        cp16(sb + GMAT + doff, B_g + (size_t)(col0 + r) * K + kbase + c * 8);
    }
}

__device__ __forceinline__ void h_mainloop(
    unsigned sb0, const __half* A_g, const __half* B_g,
    int row0, int col0, int K, int tid, float acc[4][4][4])
{
    const int lane = tid & 31;
    const int wid  = tid >> 5;
    const int wm   = wid >> 2;
    const int wn   = wid & 3;

    #pragma unroll
    for (int mi = 0; mi < 4; mi++)
        #pragma unroll
        for (int ni = 0; ni < 4; ni++)
            #pragma unroll
            for (int e = 0; e < 4; e++) acc[mi][ni][e] = 0.f;

    const int KT = K >> 5;

    h_fill(sb0,              A_g, B_g, row0, col0, K, 0,  tid); CP_COMMIT;
    h_fill(sb0 + GSTAGE,     A_g, B_g, row0, col0, K, 32, tid); CP_COMMIT;
    h_fill(sb0 + 2 * GSTAGE, A_g, B_g, row0, col0, K, 64, tid); CP_COMMIT;

    const unsigned aoff = (unsigned)((wm * 64 + (lane & 15)) * GROW + (lane >> 4) * 16);
    const unsigned boff = (unsigned)(GMAT + (wn * 32 + (lane & 15)) * GROW + (lane >> 4) * 16);

    for (int kt = 0; kt < KT; ++kt) {
        const unsigned sb = sb0 + (unsigned)(kt & 3) * GSTAGE;

        const int rem = KT - 1 - kt;
        if (rem >= 2)      CP_WAIT(2);
        else if (rem == 1) CP_WAIT(1);
        else               CP_WAIT(0);
        __syncthreads();

        if (kt + 3 < KT) {
            h_fill(sb0 + (unsigned)((kt + 3) & 3) * GSTAGE,
                   A_g, B_g, row0, col0, K, (kt + 3) * 32, tid);
            CP_COMMIT;
        }

        #pragma unroll
        for (int kc = 0; kc < 2; ++kc) {
            unsigned af[4][4], bf[2][4];
            #pragma unroll
            for (int n2 = 0; n2 < 2; ++n2)
                ldsm_x4(bf[n2], sb + boff + n2 * 16 * GROW + kc * 32);
            #pragma unroll
            for (int mi = 0; mi < 4; ++mi)
                ldsm_x4(af[mi], sb + aoff + mi * 16 * GROW + kc * 32);
            #pragma unroll
            for (int mi = 0; mi < 4; ++mi)
                #pragma unroll
                for (int n2 = 0; n2 < 2; ++n2) {
                    mma_fp16(acc[mi][2 * n2],     af[mi], bf[n2][0], bf[n2][2]);
                    mma_fp16(acc[mi][2 * n2 + 1], af[mi], bf[n2][1], bf[n2][3]);
                }
        }
    }
}

// ---------------------------------------------------------------------------
// Proj GEMM: fp32 output + bias.
// ---------------------------------------------------------------------------
__global__ __launch_bounds__(256) void hgemm(
    const __half* __restrict__ A_g, const __half* __restrict__ B_g,
    const float* __restrict__ bias, float* __restrict__ Cm,
    int M, int N, int K)
{
    extern __shared__ __align__(16) char smem[];
    const unsigned sb0 = (unsigned)__cvta_generic_to_shared(smem);
    const int tid  = threadIdx.x;
    const int lane = tid & 31;
    const int wid  = tid >> 5;
    const int wm   = wid >> 2;
    const int wn   = wid & 3;
    const int row0 = blockIdx.y * 128;
    const int col0 = blockIdx.x * 128;

    float acc[4][4][4];
    h_mainloop(sb0, A_g, B_g, row0, col0, K, tid, acc);

    const int g  = lane >> 2;
    const int tq = lane & 3;
    #pragma unroll
    for (int mi = 0; mi < 4; mi++) {
        const int r0 = row0 + wm * 64 + mi * 16 + g;
        #pragma unroll
        for (int ni = 0; ni < 4; ni++) {
            const int c = col0 + wn * 32 + (ni >> 1) * 16 + (ni & 1) * 8 + tq * 2;
            const float bz0 = bias[c], bz1 = bias[c + 1];
            *(float2*)(Cm + (size_t)r0 * N + c) =
                make_float2(acc[mi][ni][0] + bz0, acc[mi][ni][1] + bz1);
            *(float2*)(Cm + (size_t)(r0 + 8) * N + c) =
                make_float2(acc[mi][ni][2] + bz0, acc[mi][ni][3] + bz1);
        }
    }
}

// ---------------------------------------------------------------------------
// QKV GEMM with fused bias + RoPE + fp16-convert epilogue.
// q is pre-scaled by 1/8. Outputs head-contiguous fp16 q/k/v.
// ---------------------------------------------------------------------------
__global__ __launch_bounds__(256) void hgemm_qkv(
    const __half* __restrict__ A_g, const __half* __restrict__ B_g,
    const float* __restrict__ bias,
    const float* __restrict__ cosf_, const float* __restrict__ sinf_,
    __half* __restrict__ q16, __half* __restrict__ k16,
    __half* __restrict__ v16, int K)
{
    extern __shared__ __align__(16) char smem[];
    const unsigned sb0 = (unsigned)__cvta_generic_to_shared(smem);
    const int tid  = threadIdx.x;
    const int lane = tid & 31;
    const int wid  = tid >> 5;
    const int wm   = wid >> 2;
    const int wn   = wid & 3;
    const int row0 = blockIdx.y * 128;
    const int col0 = blockIdx.x * 128;

    float acc[4][4][4];
    h_mainloop(sb0, A_g, B_g, row0, col0, K, tid, acc);

    __syncthreads();
    float* sepi = (float*)smem;
    {
        const int g  = lane >> 2;
        const int tq = lane & 3;
        #pragma unroll
        for (int mi = 0; mi < 4; mi++) {
            const int r = wm * 64 + mi * 16 + g;
            #pragma unroll
            for (int ni = 0; ni < 4; ni++) {
                const int c = wn * 32 + (ni >> 1) * 16 + (ni & 1) * 8 + tq * 2;
                const float bz0 = bias[col0 + c], bz1 = bias[col0 + c + 1];
                sepi[r * EPSTR + c]           = acc[mi][ni][0] + bz0;
                sepi[r * EPSTR + c + 1]       = acc[mi][ni][1] + bz1;
                sepi[(r + 8) * EPSTR + c]     = acc[mi][ni][2] + bz0;
                sepi[(r + 8) * EPSTR + c + 1] = acc[mi][ni][3] + bz1;
            }
        }
    }
    __syncthreads();

    if (col0 < 2 * CC) {
        // q or k: RoPE + fp16
        const bool isQ = (col0 < CC);
        const int hbase = (col0 & (CC - 1)) >> 6;
        __half* dstArr = isQ ? q16 : k16;
        const float qscale = isQ ? 0.125f : 1.0f;
        #pragma unroll
        for (int it = 0; it < 32; ++it) {
            int idx = it * 256 + tid;      // 0..8191
            int r   = idx >> 6;            // 0..127
            int pc  = idx & 63;
            int head = pc >> 5, d = pc & 31;
            int c1 = head * 64 + d;
            int row = row0 + r;
            int b = row >> 11, t = row & (TT - 1);

            float v1 = sepi[r * EPSTR + c1];
            float v2 = sepi[r * EPSTR + c1 + 32];
            float ct = cosf_[t * HD2 + d];
            float st = sinf_[t * HD2 + d];
            float r1 = (v1 * ct - v2 * st) * qscale;
            float r2 = (v1 * st + v2 * ct) * qscale;

            size_t dst = ((size_t)(b * HH + hbase + head) * TT + t) * HD + d;
            dstArr[dst]       = __float2half_rn(r1);
            dstArr[dst + HD2] = __float2half_rn(r2);
        }
    } else {
        // v: fp16 convert
        const int hbase = (col0 - 2 * CC) >> 6;
        #pragma unroll
        for (int it = 0; it < 32; ++it) {
            int idx = it * 256 + tid;
            int r   = idx >> 6;
            int c   = (idx & 63) * 2;
            int head = c >> 6, d = c & 63;
            int row = row0 + r;
            int b = row >> 11, t = row & (TT - 1);
            float v1 = sepi[r * EPSTR + c];
            float v2 = sepi[r * EPSTR + c + 1];
            size_t dst = ((size_t)(b * HH + hbase + head) * TT + t) * HD + d;
            *(__half2*)(v16 + dst) = __floats2half2_rn(v1, v2);
        }
    }
}

// ---------------------------------------------------------------------------
// Flash attention, all-fp16 MMA (S single pass, PV single pass).
// cp.async double-buffered K/V. Br=64 (4 warps), Bc=64.
// Smem/stage: K 9216 + V 9216 = 18432; 2 stages = 36864.
// ---------------------------------------------------------------------------
#define KSTR2 144
#define ATT_K 0
#define ATT_V 9216
#define ATT_STAGE 18432
#define ATT_SMEM  (2*ATT_STAGE)

__device__ __forceinline__ void att_fill(
    unsigned sb, const uint4* kp, const uint4* vp, int j0, int tid)
{
    const int base = j0 * 8;
    #pragma unroll
    for (int it = 0; it < 4; ++it) {
        int idx = it * 128 + tid;
        int r = idx >> 3, c16 = (idx & 7) * 16;
        unsigned doff = (unsigned)(r * KSTR2 + c16);
        cp16(sb + ATT_K + doff, kp + base + idx);
        cp16(sb + ATT_V + doff, vp + base + idx);
    }
}

__global__ __launch_bounds__(128) void attn_mma(
    const __half* __restrict__ q16_g, const __half* __restrict__ k16_g,
    const __half* __restrict__ v16_g, __half* __restrict__ o16_g)
{
    extern __shared__ __align__(16) char asm_raw[];
    const unsigned sb0 = (unsigned)__cvta_generic_to_shared(asm_raw);

    const int iTile = gridDim.x - 1 - blockIdx.x;   // heavy tiles first
    const int bh    = blockIdx.y;
    const int b = bh / HH, h = bh % HH;
    const int tid  = threadIdx.x;
    const int lane = tid & 31;
    const int wid  = tid >> 5;
    const int wr   = wid * 16;
    const int i0   = iTile * 64;
    const int g    = lane >> 2;
    const int tq   = lane & 3;

    const size_t hoff = (size_t)bh * TT * HD;

    // stage Q through smem, ldmatrix to registers
    {
        const uint4* qp = (const uint4*)(q16_g + hoff + (size_t)i0 * HD);
        char* smc = asm_raw;
        #pragma unroll
        for (int it = 0; it < 4; ++it) {
            int idx = it * 128 + tid;
            int r = idx >> 3, c16 = (idx & 7) * 16;
            *(uint4*)(smc + ATT_K + r * KSTR2 + c16) = qp[idx];
        }
    }
    __syncthreads();

    unsigned qf[4][4];
    {
        const unsigned aoffq = (unsigned)((wr + (lane & 15)) * KSTR2 + (lane >> 4) * 16);
        #pragma unroll
        for (int kc = 0; kc < 4; ++kc)
            ldsm_x4(qf[kc], sb0 + ATT_K + aoffq + kc * 32);
    }
    __syncthreads();   // Q frags read before stage-0 fill overwrites

    float m0 = -INFINITY, m1 = -INFINITY, l0 = 0.f, l1 = 0.f;
    float o[8][4];
    #pragma unroll
    for (int ni = 0; ni < 8; ni++)
        #pragma unroll
        for (int e = 0; e < 4; e++) o[ni][e] = 0.f;

    const uint4* kp = (const uint4*)(k16_g + hoff);
    const uint4* vp = (const uint4*)(v16_g + hoff);

    att_fill(sb0, kp, vp, 0, tid);
    CP_COMMIT;

    for (int jT = 0; jT <= iTile; ++jT) {
        const int j0 = jT * 64;
        const unsigned sb = sb0 + (unsigned)(jT & 1) * ATT_STAGE;

        CP_WAIT(0);
        __syncthreads();

        if (jT < iTile) {
            att_fill(sb0 + (unsigned)((jT + 1) & 1) * ATT_STAGE, kp, vp, j0 + 64, tid);
            CP_COMMIT;
        }

        // ---- S = Q K^T (single-pass fp16) ----
        float s[8][4];
        #pragma unroll
        for (int ni = 0; ni < 8; ni++)
            #pragma unroll
            for (int e = 0; e < 4; e++) s[ni][e] = 0.f;

        #pragma unroll
        for (int kc = 0; kc < 4; ++kc) {
            #pragma unroll
            for (int n2 = 0; n2 < 4; ++n2) {
                unsigned rk[4];
                const unsigned ad = (unsigned)((n2 * 16 + (lane & 15)) * KSTR2
                                               + (lane >> 4) * 16 + kc * 32);
                ldsm_x4(rk, sb + ATT_K + ad);
                mma_fp16(s[2 * n2],     qf[kc], rk[0], rk[2]);
                mma_fp16(s[2 * n2 + 1], qf[kc], rk[1], rk[3]);
            }
        }

        if (jT == iTile) {
            const int row0 = i0 + wr + g, row1 = row0 + 8;
            #pragma unroll
            for (int ni = 0; ni < 8; ++ni) {
                const int c0 = j0 + ni * 8 + tq * 2;
                if (c0 > row0)     s[ni][0] = -INFINITY;
                if (c0 + 1 > row0) s[ni][1] = -INFINITY;
                if (c0 > row1)     s[ni][2] = -INFINITY;
                if (c0 + 1 > row1) s[ni][3] = -INFINITY;
            }
        }

        // ---- online softmax ----
        float rm0 = -INFINITY, rm1 = -INFINITY;
        #pragma unroll
        for (int ni = 0; ni < 8; ++ni) {
            rm0 = fmaxf(rm0, fmaxf(s[ni][0], s[ni][1]));
            rm1 = fmaxf(rm1, fmaxf(s[ni][2], s[ni][3]));
        }
        rm0 = fmaxf(rm0, __shfl_xor_sync(0xffffffffu, rm0, 1));
        rm0 = fmaxf(rm0, __shfl_xor_sync(0xffffffffu, rm0, 2));
        rm1 = fmaxf(rm1, __shfl_xor_sync(0xffffffffu, rm1, 1));
        rm1 = fmaxf(rm1, __shfl_xor_sync(0xffffffffu, rm1, 2));

        const float mn0 = fmaxf(m0, rm0), mn1 = fmaxf(m1, rm1);
        const float al0 = __expf(m0 - mn0), al1 = __expf(m1 - mn1);
        m0 = mn0; m1 = mn1;

        unsigned pf[8][2];
        float sum0 = 0.f, sum1 = 0.f;
        #pragma unroll
        for (int ni = 0; ni < 8; ++ni) {
            float p0 = __expf(s[ni][0] - mn0);
            float p1 = __expf(s[ni][1] - mn0);
            float p2 = __expf(s[ni][2] - mn1);
            float p3 = __expf(s[ni][3] - mn1);
            sum0 += p0 + p1; sum1 += p2 + p3;
            __half2 h01 = __floats2half2_rn(p0, p1);
            __half2 h23 = __floats2half2_rn(p2, p3);
            pf[ni][0] = *(unsigned*)&h01;
            pf[ni][1] = *(unsigned*)&h23;
        }
        sum0 += __shfl_xor_sync(0xffffffffu, sum0, 1);
        sum0 += __shfl_xor_sync(0xffffffffu, sum0, 2);
        sum1 += __shfl_xor_sync(0xffffffffu, sum1, 1);
        sum1 += __shfl_xor_sync(0xffffffffu, sum1, 2);
        l0 = l0 * al0 + sum0;
        l1 = l1 * al1 + sum1;

        #pragma unroll
        for (int ni = 0; ni < 8; ++ni) {
            o[ni][0] *= al0; o[ni][1] *= al0;
            o[ni][2] *= al1; o[ni][3] *= al1;
        }

        // ---- O += P V (single-pass fp16) ----
        #pragma unroll
        for (int kc = 0; kc < 4; ++kc) {
            unsigned ap[4] = { pf[2 * kc][0], pf[2 * kc][1], pf[2 * kc + 1][0], pf[2 * kc + 1][1] };
            #pragma unroll
            for (int n2 = 0; n2 < 4; ++n2) {
                unsigned v4[4];
                const unsigned ad = (unsigned)(ATT_V + (kc * 16 + (lane & 15)) * KSTR2
                                               + (n2 * 2 + (lane >> 4)) * 16);
                ldsm_x4_t(v4, sb + ad);
                mma_fp16(o[2 * n2],     ap, v4[0], v4[1]);
                mma_fp16(o[2 * n2 + 1], ap, v4[2], v4[3]);
            }
        }
    }

    const float inv0 = 1.f / l0, inv1 = 1.f / l1;
    const int row0 = i0 + wr + g;
    #pragma unroll
    for (int ni = 0; ni < 8; ++ni) {
        const int col = h * HD + ni * 8 + tq * 2;
        const size_t i0a = (size_t)(b * TT + row0) * CC + col;
        const size_t i1a = (size_t)(b * TT + row0 + 8) * CC + col;
        __half2 v0 = __floats2half2_rn(o[ni][0] * inv0, o[ni][1] * inv0);
        __half2 v1 = __floats2half2_rn(o[ni][2] * inv1, o[ni][3] * inv1);
        *(__half2*)(o16_g + i0a) = v0;
        *(__half2*)(o16_g + i1a) = v1;
    }
}

// ---------------------------------------------------------------------------
// Launch
// ---------------------------------------------------------------------------
extern "C" void kernel_launch(void* const* d_in, const int* in_sizes, int n_in,
                              void* d_out, int out_size)
{
    const float* x     = (const float*)d_in[0];
    const float* fcos  = (const float*)d_in[1];
    const float* fsin  = (const float*)d_in[2];
    const float* Wqkv  = (const float*)d_in[3];
    const float* bqkv  = (const float*)d_in[4];
    const float* Wproj = (const float*)d_in[5];
    const float* bproj = (const float*)d_in[6];
    float* out = (float*)d_out;

    __half *x16, *o16, *wq16, *wp16, *q16, *k16, *v16;
    cudaGetSymbolAddress((void**)&x16, g_x16);
    cudaGetSymbolAddress((void**)&o16, g_o16);
    cudaGetSymbolAddress((void**)&wq16, g_wq16);
    cudaGetSymbolAddress((void**)&wp16, g_wp16);
    cudaGetSymbolAddress((void**)&q16, g_q16);
    cudaGetSymbolAddress((void**)&k16, g_k16);
    cudaGetSymbolAddress((void**)&v16, g_v16);

    cudaFuncSetAttribute(hgemm, cudaFuncAttributeMaxDynamicSharedMemorySize, GSMEM);
    cudaFuncSetAttribute(hgemm_qkv, cudaFuncAttributeMaxDynamicSharedMemorySize, GSMEM);
    cudaFuncSetAttribute(attn_mma, cudaFuncAttributeMaxDynamicSharedMemorySize, ATT_SMEM);

    // 0) prep
    convhalf<<<(MROWS * CC) / 1024, 256>>>(x, x16);
    {
        dim3 g1(QKVW / 32, CC / 32);
        transpose_half<<<g1, 256>>>(Wqkv, wq16, CC, QKVW);
        dim3 g2(CC / 32, CC / 32);
        transpose_half<<<g2, 256>>>(Wproj, wp16, CC, CC);
    }

    // 1) QKV GEMM with fused bias+RoPE epilogue -> fp16 q/k/v
    {
        dim3 grid(QKVW / 128, MROWS / 128);   // (24, 32)
        hgemm_qkv<<<grid, 256, GSMEM>>>(x16, wq16, bqkv, fcos, fsin,
                                        q16, k16, v16, CC);
    }
    // 2) Flash attention (all fp16 MMA) -> fp16 att
    {
        dim3 grid(TT / 64, BB * HH);
        attn_mma<<<grid, 128, ATT_SMEM>>>(q16, k16, v16, o16);
    }
    // 3) out = att @ Wproj + bproj
    {
        dim3 grid(CC / 128, MROWS / 128);     // (8, 32)
        hgemm<<<grid, 256, GSMEM>>>(o16, wp16, bproj, out, MROWS, CC, CC);
    }
}